// round 11
// baseline (speedup 1.0000x reference)
#include <cuda_runtime.h>
#include <math.h>

#define DV   128
#define KP   20
#define NOUT 128
#define LNEPS 1e-5f

constexpr int VMAX = 100000;
constexpr int EMAX = 400000;

typedef unsigned long long u64;

// ---------------- scratch (device globals; no allocation allowed) ----------------
__device__ float g_npj[VMAX * KP];
__device__ float g_pd[VMAX];
__device__ float g_ps[VMAX];
__device__ float g_hv[VMAX * DV];
__device__ float g_gh[VMAX * 3 * DV];
__device__ float g_gi[VMAX * 3 * DV];
__device__ float g_lmax[VMAX];
__device__ float g_asum[VMAX];
__device__ float g_aexp[EMAX];
__device__ float g_ctx[VMAX * DV];
__device__ float g_kron[VMAX * NOUT];
__device__ float g_gru[VMAX * DV];
__device__ float g_catp[VMAX * DV];

// ---------------- packed fp32x2 helpers ----------------
__device__ __forceinline__ u64 bcast2(float x) {
    u64 r; asm("mov.b64 %0, {%1, %1};" : "=l"(r) : "f"(x)); return r;
}
__device__ __forceinline__ void fma2(u64& d, u64 a, u64 b) {
    asm("fma.rn.f32x2 %0, %1, %2, %0;" : "+l"(d) : "l"(a), "l"(b));
}
__device__ __forceinline__ float2 unpack2(u64 v) {
    float2 f; asm("mov.b64 {%0, %1}, %2;" : "=f"(f.x), "=f"(f.y) : "l"(v)); return f;
}
__device__ __forceinline__ u64 dl(double d) { return __double_as_longlong(d); }

// ---------------- reduction helpers ----------------
__device__ __forceinline__ float warpSum32(float v) {
    #pragma unroll
    for (int m = 16; m > 0; m >>= 1) v += __shfl_xor_sync(0xffffffffu, v, m);
    return v;
}
__device__ __forceinline__ float warpSum4(float v) {
    v += __shfl_xor_sync(0xffffffffu, v, 1);
    v += __shfl_xor_sync(0xffffffffu, v, 2);
    return v;
}

// ---------------- zero init ----------------
__global__ void k_zero(int V) {
    int i = blockIdx.x * blockDim.x + threadIdx.x;
    int n = V * DV;
    if (i < n) { g_ctx[i] = 0.f; g_kron[i] = 0.f; }
    if (i < V) { g_lmax[i] = 0.f; g_asum[i] = 0.f; }
}

// ---------------- per-node precompute: npj (LN+relu over 20), pd, ps ----------------
__global__ __launch_bounds__(256) void k_node_pre(
    const float* __restrict__ nf, const float* __restrict__ Wk1,
    const float* __restrict__ bk1, const float* __restrict__ g1,
    const float* __restrict__ b1, const float* __restrict__ W_edge, int V)
{
    __shared__ __align__(16) float nfs[8][DV];
    int w = threadIdx.x >> 5, lane = threadIdx.x & 31;
    int v = blockIdx.x * 8 + w;
    if (v < V) {
        float4 t = *(const float4*)&nf[(size_t)v * DV + lane * 4];
        *(float4*)&nfs[w][lane * 4] = t;
    }
    __syncwarp();
    if (v >= V) return;

    const float* base;
    int stride;
    if (lane < KP)       { base = Wk1 + lane;     stride = KP; }
    else if (lane == 20) { base = W_edge;         stride = 1;  }
    else if (lane == 21) { base = W_edge + DV;    stride = 1;  }
    else                 { base = W_edge;         stride = 0;  }

    float acc = 0.f;
    #pragma unroll 8
    for (int k = 0; k < DV; k++) acc += nfs[w][k] * base[(size_t)k * stride];

    float x = (lane < KP) ? acc + bk1[lane] : 0.f;
    float s = warpSum32((lane < KP) ? x : 0.f);
    float mu = s * (1.f / KP);
    float c = (lane < KP) ? (x - mu) : 0.f;
    float q = warpSum32(c * c);
    float rstd = rsqrtf(q * (1.f / KP) + LNEPS);
    if (lane < KP) {
        g_npj[(size_t)v * KP + lane] = fmaxf(c * rstd * g1[lane] + b1[lane], 0.f);
    } else if (lane == 20) {
        g_pd[v] = acc;
    } else if (lane == 21) {
        g_ps[v] = acc;
    }
}

// ---------------- generic tiled SGEMM (scalar FFMA, R8-proven) ----------------
template<bool BT, bool RA>
__global__ __launch_bounds__(256) void sgemm(
    const float* __restrict__ A1, const float* __restrict__ A2, int kSplit,
    const float* __restrict__ B, const float* __restrict__ bias,
    float* __restrict__ C, int M, int N, int K)
{
    __shared__ __align__(16) float As[16][128];
    __shared__ __align__(16) float Bs[16][128];
    int tid = threadIdx.x;
    int m0 = blockIdx.x * 128;
    int n0 = blockIdx.y * 128;
    int tx = tid & 15;
    int ty = tid >> 4;

    float acc[8][8];
    #pragma unroll
    for (int i = 0; i < 8; i++)
        #pragma unroll
        for (int j = 0; j < 8; j++) acc[i][j] = 0.f;

    for (int k0 = 0; k0 < K; k0 += 16) {
        __syncthreads();
        #pragma unroll
        for (int rep = 0; rep < 2; rep++) {
            int id = tid + rep * 256;
            int row = id >> 2;
            int kq = (id & 3) << 2;
            int gr = m0 + row;
            int kk = k0 + kq;
            float4 v = make_float4(0.f, 0.f, 0.f, 0.f);
            if (gr < M) {
                if (kk < kSplit) v = *(const float4*)(A1 + (size_t)gr * kSplit + kk);
                else             v = *(const float4*)(A2 + (size_t)gr * (K - kSplit) + (kk - kSplit));
            }
            if (RA) {
                v.x = fmaxf(v.x, 0.f); v.y = fmaxf(v.y, 0.f);
                v.z = fmaxf(v.z, 0.f); v.w = fmaxf(v.w, 0.f);
            }
            As[kq + 0][row] = v.x; As[kq + 1][row] = v.y;
            As[kq + 2][row] = v.z; As[kq + 3][row] = v.w;
        }
        if (!BT) {
            #pragma unroll
            for (int rep = 0; rep < 2; rep++) {
                int id = tid + rep * 256;
                int kk = id >> 5;
                int n4 = id & 31;
                float4 v = *(const float4*)(B + (size_t)(k0 + kk) * N + n0 + n4 * 4);
                *(float4*)&Bs[kk][n4 * 4] = v;
            }
        } else {
            #pragma unroll
            for (int rep = 0; rep < 2; rep++) {
                int id = tid + rep * 256;
                int n = id >> 2;
                int kq = (id & 3) << 2;
                float4 v = *(const float4*)(B + (size_t)(n0 + n) * K + k0 + kq);
                Bs[kq + 0][n] = v.x; Bs[kq + 1][n] = v.y;
                Bs[kq + 2][n] = v.z; Bs[kq + 3][n] = v.w;
            }
        }
        __syncthreads();
        #pragma unroll
        for (int k = 0; k < 16; k++) {
            float a[8], b[8];
            *(float4*)&a[0] = *(const float4*)&As[k][ty * 8];
            *(float4*)&a[4] = *(const float4*)&As[k][ty * 8 + 4];
            *(float4*)&b[0] = *(const float4*)&Bs[k][tx * 8];
            *(float4*)&b[4] = *(const float4*)&Bs[k][tx * 8 + 4];
            #pragma unroll
            for (int i = 0; i < 8; i++)
                #pragma unroll
                for (int j = 0; j < 8; j++)
                    acc[i][j] += a[i] * b[j];
        }
    }
    float bv[8];
    *(float4*)&bv[0] = *(const float4*)&bias[n0 + tx * 8];
    *(float4*)&bv[4] = *(const float4*)&bias[n0 + tx * 8 + 4];
    #pragma unroll
    for (int i = 0; i < 8; i++) {
        int gr = m0 + ty * 8 + i;
        if (gr < M) {
            float4 o0 = make_float4(acc[i][0] + bv[0], acc[i][1] + bv[1],
                                    acc[i][2] + bv[2], acc[i][3] + bv[3]);
            float4 o1 = make_float4(acc[i][4] + bv[4], acc[i][5] + bv[5],
                                    acc[i][6] + bv[6], acc[i][7] + bv[7]);
            *(float4*)(C + (size_t)gr * N + n0 + tx * 8)     = o0;
            *(float4*)(C + (size_t)gr * N + n0 + tx * 8 + 4) = o1;
        }
    }
}

// ---------------- edge attention kernels (R8-proven) ----------------
__global__ void k_elogit(const int* __restrict__ src, const int* __restrict__ dst,
                         const float* __restrict__ b_edge, int E)
{
    int e = blockIdx.x * blockDim.x + threadIdx.x;
    if (e >= E) return;
    int dv = dst[e];
    float l = fmaxf(g_pd[dv] + g_ps[src[e]] + b_edge[0], 0.f);
    g_aexp[e] = l;
    atomicMax((int*)&g_lmax[dv], __float_as_int(l));  // valid: l >= 0
}

__global__ void k_eexp(const int* __restrict__ dst, int E)
{
    int e = blockIdx.x * blockDim.x + threadIdx.x;
    if (e >= E) return;
    int dv = dst[e];
    float a = expf(g_aexp[e] - g_lmax[dv]);
    g_aexp[e] = a;
    atomicAdd(&g_asum[dv], a);
}

__global__ __launch_bounds__(256) void k_ectx(const int* __restrict__ src,
                                              const int* __restrict__ dst, int E)
{
    int e = blockIdx.x * 8 + (threadIdx.x >> 5);
    if (e >= E) return;
    int lane = threadIdx.x & 31;
    int s = src[e], dv = dst[e];
    float w = g_aexp[e] / g_asum[dv];
    float4 h = *(const float4*)&g_hv[(size_t)s * DV + lane * 4];
    float* c = &g_ctx[(size_t)dv * DV + lane * 4];
    atomicAdd(c + 0, w * h.x);
    atomicAdd(c + 1, w * h.y);
    atomicAdd(c + 2, w * h.z);
    atomicAdd(c + 3, w * h.w);
}

// ---------------- fused kron edge GEMM + LN + relu + scatter (smem-W, FFMA2) ----
// Tile: 128 edges x 128 cols. Thread: cg = tid&3 (16 cols), eg = tid>>2 (2 edges).
// Two phases of 64 cols; Wk2 column-half staged in dynamic smem each phase.
__global__ __launch_bounds__(256) void k_kron(
    const int* __restrict__ src, const int* __restrict__ dst,
    const float* __restrict__ Wk2, const float* __restrict__ bk2,
    const float* __restrict__ g2, const float* __restrict__ beta2, int E)
{
    extern __shared__ __align__(16) float sm[];
    float* a_s = sm;                        // 128 * 21
    float* b_s = a_s + 128 * 21;            // 128 * 21
    int*   dst_s = (int*)(b_s + 128 * 21);  // 128
    float* W_s = (float*)(dst_s + 128);     // 400 * 64

    int tid = threadIdx.x;
    int e0 = blockIdx.x * 128;
    int cg = tid & 3;
    int eg = tid >> 2;

    // stage npj rows for src/dst of this edge tile
    for (int idx = tid; idx < 128 * KP; idx += 256) {
        int e = idx / KP, c = idx - e * KP;
        int ge = e0 + e;
        float av = 0.f, bv = 0.f;
        if (ge < E) {
            av = g_npj[(size_t)src[ge] * KP + c];
            bv = g_npj[(size_t)dst[ge] * KP + c];
        }
        a_s[e * (KP + 1) + c] = av;
        b_s[e * (KP + 1) + c] = bv;
    }
    if (tid < 128) dst_s[tid] = (e0 + tid < E) ? dst[e0 + tid] : 0;

    u64 acc2[2][2][8] = {};   // [phase][edge][u64-col]

    #pragma unroll
    for (int p = 0; p < 2; p++) {
        __syncthreads();
        // stage W column-half [400 x 64] into smem
        for (int idx = tid; idx < 400 * 16; idx += 256) {
            int k = idx >> 4;
            int c4 = idx & 15;
            *(float4*)&W_s[k * 64 + c4 * 4] =
                *(const float4*)&Wk2[(size_t)k * NOUT + p * 64 + c4 * 4];
        }
        __syncthreads();

        const float* ar = a_s + (eg * 2) * (KP + 1);
        const float* br = b_s + (eg * 2) * (KP + 1);

        for (int i = 0; i < KP; i++) {
            float a0 = ar[i];
            float a1 = ar[(KP + 1) + i];
            const float* wbase = W_s + i * KP * 64 + cg * 16;
            #pragma unroll 5
            for (int j = 0; j < KP; j++) {
                u64 t0 = bcast2(a0 * br[j]);
                u64 t1 = bcast2(a1 * br[(KP + 1) + j]);
                const double2* wp = (const double2*)(wbase + j * 64);
                u64 w2[8];
                #pragma unroll
                for (int q = 0; q < 4; q++) {
                    int q2 = q ^ cg;                 // bank-conflict swizzle
                    double2 d = wp[q2];
                    w2[q2 * 2]     = dl(d.x);
                    w2[q2 * 2 + 1] = dl(d.y);
                }
                #pragma unroll
                for (int c = 0; c < 8; c++) {
                    fma2(acc2[p][0][c], t0, w2[c]);
                    fma2(acc2[p][1][c], t1, w2[c]);
                }
            }
        }
    }

    // epilogue: bias + LN(128 over 4 lanes x 32 cols) + relu + atomic scatter
    #pragma unroll
    for (int e = 0; e < 2; e++) {
        int le = eg * 2 + e;
        int ge = e0 + le;
        float pre[32];
        float s = 0.f;
        #pragma unroll
        for (int p = 0; p < 2; p++)
            #pragma unroll
            for (int c = 0; c < 8; c++) {
                float2 v = unpack2(acc2[p][e][c]);
                int col = p * 64 + cg * 16 + c * 2;
                pre[p * 16 + c * 2]     = v.x + bk2[col];
                pre[p * 16 + c * 2 + 1] = v.y + bk2[col + 1];
                s += pre[p * 16 + c * 2] + pre[p * 16 + c * 2 + 1];
            }
        s = warpSum4(s);
        float mu = s * (1.f / NOUT);
        float q = 0.f;
        #pragma unroll
        for (int c = 0; c < 32; c++) { float d = pre[c] - mu; q += d * d; }
        q = warpSum4(q);
        float rstd = rsqrtf(q * (1.f / NOUT) + LNEPS);
        if (ge < E) {
            float* outp = &g_kron[(size_t)dst_s[le] * NOUT];
            #pragma unroll
            for (int p = 0; p < 2; p++)
                #pragma unroll
                for (int c = 0; c < 16; c++) {
                    int col = p * 64 + cg * 16 + c;
                    float y = fmaxf((pre[p * 16 + c] - mu) * rstd * g2[col] + beta2[col], 0.f);
                    atomicAdd(outp + col, y);
                }
        }
    }
}

// ---------------- GRU combine + relu + LN(128) ----------------
__global__ __launch_bounds__(128) void k_gru(const float* __restrict__ nf,
                                             const float* __restrict__ lng,
                                             const float* __restrict__ lnb, int V)
{
    int v = blockIdx.x;
    int d = threadIdx.x;
    int wid = d >> 5, lane = d & 31;
    const float* gi = g_gi + (size_t)v * 3 * DV;
    const float* gh = g_gh + (size_t)v * 3 * DV;
    float r = 1.f / (1.f + expf(-(gi[d] + gh[d])));
    float z = 1.f / (1.f + expf(-(gi[DV + d] + gh[DV + d])));
    float nn = tanhf(gi[2 * DV + d] + r * gh[2 * DV + d]);
    float h = (1.f - z) * nn + z * nf[(size_t)v * DV + d];
    float x = fmaxf(h, 0.f);

    __shared__ float red[4];
    float s = warpSum32(x);
    if (lane == 0) red[wid] = s;
    __syncthreads();
    float mu = (red[0] + red[1] + red[2] + red[3]) * (1.f / DV);
    __syncthreads();
    float c = x - mu;
    float q = warpSum32(c * c);
    if (lane == 0) red[wid] = q;
    __syncthreads();
    float var = (red[0] + red[1] + red[2] + red[3]) * (1.f / DV);
    g_gru[(size_t)v * DV + d] = c * rsqrtf(var + LNEPS) * lng[d] + lnb[d];
}

// ---------------- final LN + relu ----------------
__global__ __launch_bounds__(128) void k_final(const float* __restrict__ lncg,
                                               const float* __restrict__ lncb,
                                               float* __restrict__ out, int V)
{
    int v = blockIdx.x;
    int d = threadIdx.x;
    int wid = d >> 5, lane = d & 31;
    float x = g_catp[(size_t)v * DV + d];

    __shared__ float red[4];
    float s = warpSum32(x);
    if (lane == 0) red[wid] = s;
    __syncthreads();
    float mu = (red[0] + red[1] + red[2] + red[3]) * (1.f / DV);
    __syncthreads();
    float c = x - mu;
    float q = warpSum32(c * c);
    if (lane == 0) red[wid] = q;
    __syncthreads();
    float var = (red[0] + red[1] + red[2] + red[3]) * (1.f / DV);
    float y = c * rsqrtf(var + LNEPS) * lncg[d] + lncb[d];
    out[(size_t)v * DV + d] = fmaxf(y, 0.f);
}

// ---------------- host ----------------
static inline int cdiv(int a, int b) { return (a + b - 1) / b; }

extern "C" void kernel_launch(void* const* d_in, const int* in_sizes, int n_in,
                              void* d_out, int out_size)
{
    const float* nf     = (const float*)d_in[0];
    const int*   src    = (const int*)d_in[1];
    const int*   dst    = (const int*)d_in[2];
    const float* W_edge = (const float*)d_in[3];
    const float* b_edge = (const float*)d_in[4];
    const float* W_pn   = (const float*)d_in[5];
    const float* b_pn   = (const float*)d_in[6];
    const float* W_ih   = (const float*)d_in[7];
    const float* b_ih   = (const float*)d_in[8];
    const float* W_hh   = (const float*)d_in[9];
    const float* b_hh   = (const float*)d_in[10];
    const float* ln_g   = (const float*)d_in[11];
    const float* ln_b   = (const float*)d_in[12];
    const float* Wk1    = (const float*)d_in[13];
    const float* bk1    = (const float*)d_in[14];
    const float* lnk1_g = (const float*)d_in[15];
    const float* lnk1_b = (const float*)d_in[16];
    const float* Wk2    = (const float*)d_in[17];
    const float* bk2    = (const float*)d_in[18];
    const float* lnk2_g = (const float*)d_in[19];
    const float* lnk2_b = (const float*)d_in[20];
    const float* Wc     = (const float*)d_in[21];
    const float* bc     = (const float*)d_in[22];
    const float* lnc_g  = (const float*)d_in[23];
    const float* lnc_b  = (const float*)d_in[24];
    float* out = (float*)d_out;

    int V = in_sizes[0] / DV;
    int E = in_sizes[1];

    float *p_hv, *p_gh, *p_gi, *p_ctx, *p_gru, *p_kron, *p_catp;
    cudaGetSymbolAddress((void**)&p_hv,   g_hv);
    cudaGetSymbolAddress((void**)&p_gh,   g_gh);
    cudaGetSymbolAddress((void**)&p_gi,   g_gi);
    cudaGetSymbolAddress((void**)&p_ctx,  g_ctx);
    cudaGetSymbolAddress((void**)&p_gru,  g_gru);
    cudaGetSymbolAddress((void**)&p_kron, g_kron);
    cudaGetSymbolAddress((void**)&p_catp, g_catp);

    // k_kron dynamic smem: a_s/b_s (2*128*21) + dst (128 ints) + W half (400*64)
    const int kronSmem = (2 * 128 * 21 + 128 + 400 * 64) * 4;
    cudaFuncSetAttribute(k_kron, cudaFuncAttributeMaxDynamicSharedMemorySize, kronSmem);

    k_zero<<<cdiv(V * DV, 256), 256>>>(V);
    k_node_pre<<<cdiv(V, 8), 256>>>(nf, Wk1, bk1, lnk1_g, lnk1_b, W_edge, V);

    sgemm<false, false><<<dim3(cdiv(V, 128), 1), 256>>>(nf, nf, DV, W_pn, b_pn, p_hv, V, DV, DV);
    sgemm<true, false><<<dim3(cdiv(V, 128), 3), 256>>>(nf, nf, DV, W_hh, b_hh, p_gh, V, 3 * DV, DV);

    k_elogit<<<cdiv(E, 256), 256>>>(src, dst, b_edge, E);
    k_eexp<<<cdiv(E, 256), 256>>>(dst, E);
    k_ectx<<<cdiv(E, 8), 256>>>(src, dst, E);

    k_kron<<<cdiv(E, 128), 256, kronSmem>>>(src, dst, Wk2, bk2, lnk2_g, lnk2_b, E);

    sgemm<true, true><<<dim3(cdiv(V, 128), 3), 256>>>(p_ctx, p_ctx, DV, W_ih, b_ih, p_gi, V, 3 * DV, DV);

    k_gru<<<V, 128>>>(nf, ln_g, ln_b, V);

    sgemm<false, false><<<dim3(cdiv(V, 128), 1), 256>>>(p_gru, p_kron, DV, Wc, bc, p_catp, V, DV, 2 * DV);

    k_final<<<V, 128>>>(lnc_g, lnc_b, out, V);
}

// round 12
// speedup vs baseline: 9.4708x; 9.4708x over previous
#include <cuda_runtime.h>
#include <math.h>

#define DV   128
#define KP   20
#define NOUT 128
#define LNEPS 1e-5f

constexpr int VMAX = 100000;
constexpr int EMAX = 400000;

typedef unsigned long long u64;

// ---------------- scratch (device globals; no allocation allowed) ----------------
__device__ float g_npj[VMAX * KP];
__device__ float g_pd[VMAX];
__device__ float g_ps[VMAX];
__device__ float g_hv[VMAX * DV];
__device__ float g_gh[VMAX * 3 * DV];
__device__ float g_gi[VMAX * 3 * DV];
__device__ float g_lmax[VMAX];
__device__ float g_asum[VMAX];
__device__ float g_aexp[EMAX];
__device__ float g_ctx[VMAX * DV];
__device__ float g_kron[VMAX * NOUT];
__device__ float g_gru[VMAX * DV];
__device__ float g_catp[VMAX * DV];

// ---------------- packed fp32x2 helpers ----------------
__device__ __forceinline__ u64 bcast2(float x) {
    u64 r; asm("mov.b64 %0, {%1, %1};" : "=l"(r) : "f"(x)); return r;
}
__device__ __forceinline__ void fma2(u64& d, u64 a, u64 b) {
    asm("fma.rn.f32x2 %0, %1, %2, %0;" : "+l"(d) : "l"(a), "l"(b));
}
__device__ __forceinline__ float2 unpack2(u64 v) {
    float2 f; asm("mov.b64 {%0, %1}, %2;" : "=f"(f.x), "=f"(f.y) : "l"(v)); return f;
}
__device__ __forceinline__ u64 dl(double d) { return __double_as_longlong(d); }

__device__ __forceinline__ void red4(float* p, float x, float y, float z, float w) {
    asm volatile("red.global.add.v4.f32 [%0], {%1, %2, %3, %4};"
                 :: "l"(p), "f"(x), "f"(y), "f"(z), "f"(w) : "memory");
}

// ---------------- reduction helpers ----------------
__device__ __forceinline__ float warpSum32(float v) {
    #pragma unroll
    for (int m = 16; m > 0; m >>= 1) v += __shfl_xor_sync(0xffffffffu, v, m);
    return v;
}
__device__ __forceinline__ float warpSum16(float v) {
    #pragma unroll
    for (int m = 8; m > 0; m >>= 1) v += __shfl_xor_sync(0xffffffffu, v, m);
    return v;
}

// ---------------- zero init ----------------
__global__ void k_zero(int V) {
    int i = blockIdx.x * blockDim.x + threadIdx.x;
    int n = V * DV;
    if (i < n) { g_ctx[i] = 0.f; g_kron[i] = 0.f; }
    if (i < V) { g_lmax[i] = 0.f; g_asum[i] = 0.f; }
}

// ---------------- per-node precompute: npj (LN+relu over 20), pd, ps ----------------
__global__ __launch_bounds__(256) void k_node_pre(
    const float* __restrict__ nf, const float* __restrict__ Wk1,
    const float* __restrict__ bk1, const float* __restrict__ g1,
    const float* __restrict__ b1, const float* __restrict__ W_edge, int V)
{
    __shared__ __align__(16) float nfs[8][DV];
    int w = threadIdx.x >> 5, lane = threadIdx.x & 31;
    int v = blockIdx.x * 8 + w;
    if (v < V) {
        float4 t = *(const float4*)&nf[(size_t)v * DV + lane * 4];
        *(float4*)&nfs[w][lane * 4] = t;
    }
    __syncwarp();
    if (v >= V) return;

    const float* base;
    int stride;
    if (lane < KP)       { base = Wk1 + lane;     stride = KP; }
    else if (lane == 20) { base = W_edge;         stride = 1;  }
    else if (lane == 21) { base = W_edge + DV;    stride = 1;  }
    else                 { base = W_edge;         stride = 0;  }

    float acc = 0.f;
    #pragma unroll 8
    for (int k = 0; k < DV; k++) acc += nfs[w][k] * base[(size_t)k * stride];

    float x = (lane < KP) ? acc + bk1[lane] : 0.f;
    float s = warpSum32((lane < KP) ? x : 0.f);
    float mu = s * (1.f / KP);
    float c = (lane < KP) ? (x - mu) : 0.f;
    float q = warpSum32(c * c);
    float rstd = rsqrtf(q * (1.f / KP) + LNEPS);
    if (lane < KP) {
        g_npj[(size_t)v * KP + lane] = fmaxf(c * rstd * g1[lane] + b1[lane], 0.f);
    } else if (lane == 20) {
        g_pd[v] = acc;
    } else if (lane == 21) {
        g_ps[v] = acc;
    }
}

// ---------------- generic tiled SGEMM (scalar FFMA, R8-proven) ----------------
template<bool BT, bool RA>
__global__ __launch_bounds__(256) void sgemm(
    const float* __restrict__ A1, const float* __restrict__ A2, int kSplit,
    const float* __restrict__ B, const float* __restrict__ bias,
    float* __restrict__ C, int M, int N, int K)
{
    __shared__ __align__(16) float As[16][128];
    __shared__ __align__(16) float Bs[16][128];
    int tid = threadIdx.x;
    int m0 = blockIdx.x * 128;
    int n0 = blockIdx.y * 128;
    int tx = tid & 15;
    int ty = tid >> 4;

    float acc[8][8];
    #pragma unroll
    for (int i = 0; i < 8; i++)
        #pragma unroll
        for (int j = 0; j < 8; j++) acc[i][j] = 0.f;

    for (int k0 = 0; k0 < K; k0 += 16) {
        __syncthreads();
        #pragma unroll
        for (int rep = 0; rep < 2; rep++) {
            int id = tid + rep * 256;
            int row = id >> 2;
            int kq = (id & 3) << 2;
            int gr = m0 + row;
            int kk = k0 + kq;
            float4 v = make_float4(0.f, 0.f, 0.f, 0.f);
            if (gr < M) {
                if (kk < kSplit) v = *(const float4*)(A1 + (size_t)gr * kSplit + kk);
                else             v = *(const float4*)(A2 + (size_t)gr * (K - kSplit) + (kk - kSplit));
            }
            if (RA) {
                v.x = fmaxf(v.x, 0.f); v.y = fmaxf(v.y, 0.f);
                v.z = fmaxf(v.z, 0.f); v.w = fmaxf(v.w, 0.f);
            }
            As[kq + 0][row] = v.x; As[kq + 1][row] = v.y;
            As[kq + 2][row] = v.z; As[kq + 3][row] = v.w;
        }
        if (!BT) {
            #pragma unroll
            for (int rep = 0; rep < 2; rep++) {
                int id = tid + rep * 256;
                int kk = id >> 5;
                int n4 = id & 31;
                float4 v = *(const float4*)(B + (size_t)(k0 + kk) * N + n0 + n4 * 4);
                *(float4*)&Bs[kk][n4 * 4] = v;
            }
        } else {
            #pragma unroll
            for (int rep = 0; rep < 2; rep++) {
                int id = tid + rep * 256;
                int n = id >> 2;
                int kq = (id & 3) << 2;
                float4 v = *(const float4*)(B + (size_t)(n0 + n) * K + k0 + kq);
                Bs[kq + 0][n] = v.x; Bs[kq + 1][n] = v.y;
                Bs[kq + 2][n] = v.z; Bs[kq + 3][n] = v.w;
            }
        }
        __syncthreads();
        #pragma unroll
        for (int k = 0; k < 16; k++) {
            float a[8], b[8];
            *(float4*)&a[0] = *(const float4*)&As[k][ty * 8];
            *(float4*)&a[4] = *(const float4*)&As[k][ty * 8 + 4];
            *(float4*)&b[0] = *(const float4*)&Bs[k][tx * 8];
            *(float4*)&b[4] = *(const float4*)&Bs[k][tx * 8 + 4];
            #pragma unroll
            for (int i = 0; i < 8; i++)
                #pragma unroll
                for (int j = 0; j < 8; j++)
                    acc[i][j] += a[i] * b[j];
        }
    }
    float bv[8];
    *(float4*)&bv[0] = *(const float4*)&bias[n0 + tx * 8];
    *(float4*)&bv[4] = *(const float4*)&bias[n0 + tx * 8 + 4];
    #pragma unroll
    for (int i = 0; i < 8; i++) {
        int gr = m0 + ty * 8 + i;
        if (gr < M) {
            float4 o0 = make_float4(acc[i][0] + bv[0], acc[i][1] + bv[1],
                                    acc[i][2] + bv[2], acc[i][3] + bv[3]);
            float4 o1 = make_float4(acc[i][4] + bv[4], acc[i][5] + bv[5],
                                    acc[i][6] + bv[6], acc[i][7] + bv[7]);
            *(float4*)(C + (size_t)gr * N + n0 + tx * 8)     = o0;
            *(float4*)(C + (size_t)gr * N + n0 + tx * 8 + 4) = o1;
        }
    }
}

// ---------------- edge attention kernels ----------------
__global__ void k_elogit(const int* __restrict__ src, const int* __restrict__ dst,
                         const float* __restrict__ b_edge, int E)
{
    int e = blockIdx.x * blockDim.x + threadIdx.x;
    if (e >= E) return;
    int dv = dst[e];
    float l = fmaxf(g_pd[dv] + g_ps[src[e]] + b_edge[0], 0.f);
    g_aexp[e] = l;
    atomicMax((int*)&g_lmax[dv], __float_as_int(l));  // valid: l >= 0
}

__global__ void k_eexp(const int* __restrict__ dst, int E)
{
    int e = blockIdx.x * blockDim.x + threadIdx.x;
    if (e >= E) return;
    int dv = dst[e];
    float a = expf(g_aexp[e] - g_lmax[dv]);
    g_aexp[e] = a;
    atomicAdd(&g_asum[dv], a);
}

__global__ __launch_bounds__(256) void k_ectx(const int* __restrict__ src,
                                              const int* __restrict__ dst, int E)
{
    int e = blockIdx.x * 8 + (threadIdx.x >> 5);
    if (e >= E) return;
    int lane = threadIdx.x & 31;
    int s = src[e], dv = dst[e];
    float w = g_aexp[e] / g_asum[dv];
    float4 h = *(const float4*)&g_hv[(size_t)s * DV + lane * 4];
    float* c = &g_ctx[(size_t)dv * DV + lane * 4];
    red4(c, w * h.x, w * h.y, w * h.z, w * h.w);
}

// ---------------- fused kron edge GEMM + LN + relu + scatter ----------------
// R8 tile: 64 edges x 128 outs; thread = 4 edges x 8 outs; ot=tid&15, et=tid>>4.
// Inner loop converted to packed fma2: acc u64[4][4] (same 32-reg footprint).
__global__ __launch_bounds__(256) void k_kron(
    const int* __restrict__ src, const int* __restrict__ dst,
    const float* __restrict__ Wk2, const float* __restrict__ bk2,
    const float* __restrict__ g2, const float* __restrict__ beta2, int E)
{
    __shared__ float a_s[64][KP];
    __shared__ float b_s[64][KP];
    __shared__ int dst_s[64];
    int tid = threadIdx.x;
    int e0 = blockIdx.x * 64;

    for (int idx = tid; idx < 64 * KP; idx += 256) {
        int e = idx / KP, c = idx % KP;
        int ge = e0 + e;
        float av = 0.f, bv = 0.f;
        if (ge < E) {
            av = g_npj[(size_t)src[ge] * KP + c];
            bv = g_npj[(size_t)dst[ge] * KP + c];
        }
        a_s[e][c] = av;
        b_s[e][c] = bv;
    }
    if (tid < 64) dst_s[tid] = (e0 + tid < E) ? dst[e0 + tid] : 0;
    __syncthreads();

    int ot = tid & 15;
    int et = tid >> 4;

    u64 acc2[4][4] = {};

    for (int i = 0; i < KP; i++) {
        float a0 = a_s[et * 4 + 0][i];
        float a1 = a_s[et * 4 + 1][i];
        float a2 = a_s[et * 4 + 2][i];
        float a3 = a_s[et * 4 + 3][i];
        #pragma unroll 4
        for (int j = 0; j < KP; j++) {
            int k = i * KP + j;
            const double2* wp = (const double2*)(Wk2 + (size_t)k * NOUT + ot * 8);
            double2 wA = wp[0], wB = wp[1];
            u64 w2[4] = { dl(wA.x), dl(wA.y), dl(wB.x), dl(wB.y) };
            u64 t0 = bcast2(a0 * b_s[et * 4 + 0][j]);
            u64 t1 = bcast2(a1 * b_s[et * 4 + 1][j]);
            u64 t2 = bcast2(a2 * b_s[et * 4 + 2][j]);
            u64 t3 = bcast2(a3 * b_s[et * 4 + 3][j]);
            #pragma unroll
            for (int c = 0; c < 4; c++) {
                fma2(acc2[0][c], t0, w2[c]);
                fma2(acc2[1][c], t1, w2[c]);
                fma2(acc2[2][c], t2, w2[c]);
                fma2(acc2[3][c], t3, w2[c]);
            }
        }
    }

    // epilogue: bias + LN(128) + relu + red.v4 scatter
    float bk[8], gg[8], bb[8];
    *(float4*)&bk[0] = *(const float4*)&bk2[ot * 8];
    *(float4*)&bk[4] = *(const float4*)&bk2[ot * 8 + 4];
    *(float4*)&gg[0] = *(const float4*)&g2[ot * 8];
    *(float4*)&gg[4] = *(const float4*)&g2[ot * 8 + 4];
    *(float4*)&bb[0] = *(const float4*)&beta2[ot * 8];
    *(float4*)&bb[4] = *(const float4*)&beta2[ot * 8 + 4];

    #pragma unroll
    for (int e = 0; e < 4; e++) {
        int le = et * 4 + e;
        int ge = e0 + le;
        float pre[8];
        float s = 0.f;
        #pragma unroll
        for (int c = 0; c < 4; c++) {
            float2 p = unpack2(acc2[e][c]);
            pre[c * 2]     = p.x + bk[c * 2];
            pre[c * 2 + 1] = p.y + bk[c * 2 + 1];
            s += pre[c * 2] + pre[c * 2 + 1];
        }
        s = warpSum16(s);
        float mu = s * (1.f / NOUT);
        float q = 0.f;
        #pragma unroll
        for (int c = 0; c < 8; c++) { float d = pre[c] - mu; q += d * d; }
        q = warpSum16(q);
        float rstd = rsqrtf(q * (1.f / NOUT) + LNEPS);
        if (ge < E) {
            float* outp = &g_kron[(size_t)dst_s[le] * NOUT + ot * 8];
            float y[8];
            #pragma unroll
            for (int c = 0; c < 8; c++)
                y[c] = fmaxf((pre[c] - mu) * rstd * gg[c] + bb[c], 0.f);
            red4(outp,     y[0], y[1], y[2], y[3]);
            red4(outp + 4, y[4], y[5], y[6], y[7]);
        }
    }
}

// ---------------- GRU combine + relu + LN(128) ----------------
__global__ __launch_bounds__(128) void k_gru(const float* __restrict__ nf,
                                             const float* __restrict__ lng,
                                             const float* __restrict__ lnb, int V)
{
    int v = blockIdx.x;
    int d = threadIdx.x;
    int wid = d >> 5, lane = d & 31;
    const float* gi = g_gi + (size_t)v * 3 * DV;
    const float* gh = g_gh + (size_t)v * 3 * DV;
    float r = 1.f / (1.f + expf(-(gi[d] + gh[d])));
    float z = 1.f / (1.f + expf(-(gi[DV + d] + gh[DV + d])));
    float nn = tanhf(gi[2 * DV + d] + r * gh[2 * DV + d]);
    float h = (1.f - z) * nn + z * nf[(size_t)v * DV + d];
    float x = fmaxf(h, 0.f);

    __shared__ float red[4];
    float s = warpSum32(x);
    if (lane == 0) red[wid] = s;
    __syncthreads();
    float mu = (red[0] + red[1] + red[2] + red[3]) * (1.f / DV);
    __syncthreads();
    float c = x - mu;
    float q = warpSum32(c * c);
    if (lane == 0) red[wid] = q;
    __syncthreads();
    float var = (red[0] + red[1] + red[2] + red[3]) * (1.f / DV);
    g_gru[(size_t)v * DV + d] = c * rsqrtf(var + LNEPS) * lng[d] + lnb[d];
}

// ---------------- final LN + relu ----------------
__global__ __launch_bounds__(128) void k_final(const float* __restrict__ lncg,
                                               const float* __restrict__ lncb,
                                               float* __restrict__ out, int V)
{
    int v = blockIdx.x;
    int d = threadIdx.x;
    int wid = d >> 5, lane = d & 31;
    float x = g_catp[(size_t)v * DV + d];

    __shared__ float red[4];
    float s = warpSum32(x);
    if (lane == 0) red[wid] = s;
    __syncthreads();
    float mu = (red[0] + red[1] + red[2] + red[3]) * (1.f / DV);
    __syncthreads();
    float c = x - mu;
    float q = warpSum32(c * c);
    if (lane == 0) red[wid] = q;
    __syncthreads();
    float var = (red[0] + red[1] + red[2] + red[3]) * (1.f / DV);
    float y = c * rsqrtf(var + LNEPS) * lncg[d] + lncb[d];
    out[(size_t)v * DV + d] = fmaxf(y, 0.f);
}

// ---------------- host ----------------
static inline int cdiv(int a, int b) { return (a + b - 1) / b; }

extern "C" void kernel_launch(void* const* d_in, const int* in_sizes, int n_in,
                              void* d_out, int out_size)
{
    const float* nf     = (const float*)d_in[0];
    const int*   src    = (const int*)d_in[1];
    const int*   dst    = (const int*)d_in[2];
    const float* W_edge = (const float*)d_in[3];
    const float* b_edge = (const float*)d_in[4];
    const float* W_pn   = (const float*)d_in[5];
    const float* b_pn   = (const float*)d_in[6];
    const float* W_ih   = (const float*)d_in[7];
    const float* b_ih   = (const float*)d_in[8];
    const float* W_hh   = (const float*)d_in[9];
    const float* b_hh   = (const float*)d_in[10];
    const float* ln_g   = (const float*)d_in[11];
    const float* ln_b   = (const float*)d_in[12];
    const float* Wk1    = (const float*)d_in[13];
    const float* bk1    = (const float*)d_in[14];
    const float* lnk1_g = (const float*)d_in[15];
    const float* lnk1_b = (const float*)d_in[16];
    const float* Wk2    = (const float*)d_in[17];
    const float* bk2    = (const float*)d_in[18];
    const float* lnk2_g = (const float*)d_in[19];
    const float* lnk2_b = (const float*)d_in[20];
    const float* Wc     = (const float*)d_in[21];
    const float* bc     = (const float*)d_in[22];
    const float* lnc_g  = (const float*)d_in[23];
    const float* lnc_b  = (const float*)d_in[24];
    float* out = (float*)d_out;

    int V = in_sizes[0] / DV;
    int E = in_sizes[1];

    float *p_hv, *p_gh, *p_gi, *p_ctx, *p_gru, *p_kron, *p_catp;
    cudaGetSymbolAddress((void**)&p_hv,   g_hv);
    cudaGetSymbolAddress((void**)&p_gh,   g_gh);
    cudaGetSymbolAddress((void**)&p_gi,   g_gi);
    cudaGetSymbolAddress((void**)&p_ctx,  g_ctx);
    cudaGetSymbolAddress((void**)&p_gru,  g_gru);
    cudaGetSymbolAddress((void**)&p_kron, g_kron);
    cudaGetSymbolAddress((void**)&p_catp, g_catp);

    k_zero<<<cdiv(V * DV, 256), 256>>>(V);
    k_node_pre<<<cdiv(V, 8), 256>>>(nf, Wk1, bk1, lnk1_g, lnk1_b, W_edge, V);

    sgemm<false, false><<<dim3(cdiv(V, 128), 1), 256>>>(nf, nf, DV, W_pn, b_pn, p_hv, V, DV, DV);
    sgemm<true, false><<<dim3(cdiv(V, 128), 3), 256>>>(nf, nf, DV, W_hh, b_hh, p_gh, V, 3 * DV, DV);

    k_elogit<<<cdiv(E, 256), 256>>>(src, dst, b_edge, E);
    k_eexp<<<cdiv(E, 256), 256>>>(dst, E);
    k_ectx<<<cdiv(E, 8), 256>>>(src, dst, E);

    k_kron<<<cdiv(E, 64), 256>>>(src, dst, Wk2, bk2, lnk2_g, lnk2_b, E);

    sgemm<true, true><<<dim3(cdiv(V, 128), 3), 256>>>(p_ctx, p_ctx, DV, W_ih, b_ih, p_gi, V, 3 * DV, DV);

    k_gru<<<V, 128>>>(nf, ln_g, ln_b, V);

    sgemm<false, false><<<dim3(cdiv(V, 128), 1), 256>>>(p_gru, p_kron, DV, Wc, bc, p_catp, V, DV, 2 * DV);

    k_final<<<V, 128>>>(lnc_g, lnc_b, out, V);
}

// round 13
// speedup vs baseline: 9.8058x; 1.0354x over previous
#include <cuda_runtime.h>
#include <math.h>

#define DV   128
#define KP   20
#define NOUT 128
#define LNEPS 1e-5f

constexpr int VMAX = 100000;
constexpr int EMAX = 400000;

typedef unsigned long long u64;

// ---------------- scratch (device globals; no allocation allowed) ----------------
__device__ float g_npj[VMAX * KP];
__device__ float g_pd[VMAX];
__device__ float g_ps[VMAX];
__device__ float g_hv[VMAX * DV];
__device__ float g_gh[VMAX * 3 * DV];
__device__ float g_gi[VMAX * 3 * DV];
__device__ float g_asum[VMAX];
__device__ float g_aexp[EMAX];
__device__ float g_ctx[VMAX * DV];
__device__ float g_kron[VMAX * NOUT];
__device__ float g_gru[VMAX * DV];

// ---------------- packed fp32x2 helpers ----------------
__device__ __forceinline__ u64 bcast2(float x) {
    u64 r; asm("mov.b64 %0, {%1, %1};" : "=l"(r) : "f"(x)); return r;
}
__device__ __forceinline__ void fma2(u64& d, u64 a, u64 b) {
    asm("fma.rn.f32x2 %0, %1, %2, %0;" : "+l"(d) : "l"(a), "l"(b));
}
__device__ __forceinline__ float2 unpack2(u64 v) {
    float2 f; asm("mov.b64 {%0, %1}, %2;" : "=f"(f.x), "=f"(f.y) : "l"(v)); return f;
}
__device__ __forceinline__ u64 dl(double d) { return __double_as_longlong(d); }

__device__ __forceinline__ void red4(float* p, float x, float y, float z, float w) {
    asm volatile("red.global.add.v4.f32 [%0], {%1, %2, %3, %4};"
                 :: "l"(p), "f"(x), "f"(y), "f"(z), "f"(w) : "memory");
}

// ---------------- reduction helpers ----------------
__device__ __forceinline__ float warpSum32(float v) {
    #pragma unroll
    for (int m = 16; m > 0; m >>= 1) v += __shfl_xor_sync(0xffffffffu, v, m);
    return v;
}
__device__ __forceinline__ float warpSum16(float v) {
    #pragma unroll
    for (int m = 8; m > 0; m >>= 1) v += __shfl_xor_sync(0xffffffffu, v, m);
    return v;
}

// ---------------- zero init ----------------
__global__ void k_zero(int V) {
    int i = blockIdx.x * blockDim.x + threadIdx.x;
    int n = V * DV;
    if (i < n) { g_ctx[i] = 0.f; g_kron[i] = 0.f; }
    if (i < V) { g_asum[i] = 0.f; }
}

// ---------------- per-node precompute: npj (LN+relu over 20), pd, ps ----------------
__global__ __launch_bounds__(256) void k_node_pre(
    const float* __restrict__ nf, const float* __restrict__ Wk1,
    const float* __restrict__ bk1, const float* __restrict__ g1,
    const float* __restrict__ b1, const float* __restrict__ W_edge, int V)
{
    __shared__ __align__(16) float nfs[8][DV];
    int w = threadIdx.x >> 5, lane = threadIdx.x & 31;
    int v = blockIdx.x * 8 + w;
    if (v < V) {
        float4 t = *(const float4*)&nf[(size_t)v * DV + lane * 4];
        *(float4*)&nfs[w][lane * 4] = t;
    }
    __syncwarp();
    if (v >= V) return;

    const float* base;
    int stride;
    if (lane < KP)       { base = Wk1 + lane;     stride = KP; }
    else if (lane == 20) { base = W_edge;         stride = 1;  }
    else if (lane == 21) { base = W_edge + DV;    stride = 1;  }
    else                 { base = W_edge;         stride = 0;  }

    float acc = 0.f;
    #pragma unroll 8
    for (int k = 0; k < DV; k++) acc += nfs[w][k] * base[(size_t)k * stride];

    float x = (lane < KP) ? acc + bk1[lane] : 0.f;
    float s = warpSum32((lane < KP) ? x : 0.f);
    float mu = s * (1.f / KP);
    float c = (lane < KP) ? (x - mu) : 0.f;
    float q = warpSum32(c * c);
    float rstd = rsqrtf(q * (1.f / KP) + LNEPS);
    if (lane < KP) {
        g_npj[(size_t)v * KP + lane] = fmaxf(c * rstd * g1[lane] + b1[lane], 0.f);
    } else if (lane == 20) {
        g_pd[v] = acc;
    } else if (lane == 21) {
        g_ps[v] = acc;
    }
}

// ---------------- double-buffered tiled SGEMM ----------------
// C = op(A) @ B + bias; optionally fused LN+relu epilogue (row = half-warp).
template<bool BT, bool RA, bool LNOUT>
__global__ __launch_bounds__(256, 2) void sgemm(
    const float* __restrict__ A1, const float* __restrict__ A2, int kSplit,
    const float* __restrict__ B, const float* __restrict__ bias,
    float* __restrict__ C, int M, int N, int K,
    const float* __restrict__ lnG, const float* __restrict__ lnB)
{
    __shared__ __align__(16) float As[2][16][128];
    __shared__ __align__(16) float Bs[2][16][128];
    int tid = threadIdx.x;
    int m0 = blockIdx.x * 128;
    int n0 = blockIdx.y * 128;
    int tx = tid & 15;
    int ty = tid >> 4;

    float acc[8][8];
    #pragma unroll
    for (int i = 0; i < 8; i++)
        #pragma unroll
        for (int j = 0; j < 8; j++) acc[i][j] = 0.f;

    float4 ra[2], rb[2];

    auto ldA = [&](int k0) {
        #pragma unroll
        for (int rep = 0; rep < 2; rep++) {
            int id = tid + rep * 256;
            int row = id >> 2;
            int kq = (id & 3) << 2;
            int gr = m0 + row;
            int kk = k0 + kq;
            float4 v = make_float4(0.f, 0.f, 0.f, 0.f);
            if (gr < M) {
                if (kk < kSplit) v = *(const float4*)(A1 + (size_t)gr * kSplit + kk);
                else             v = *(const float4*)(A2 + (size_t)gr * (K - kSplit) + (kk - kSplit));
            }
            if (RA) {
                v.x = fmaxf(v.x, 0.f); v.y = fmaxf(v.y, 0.f);
                v.z = fmaxf(v.z, 0.f); v.w = fmaxf(v.w, 0.f);
            }
            ra[rep] = v;
        }
    };
    auto stA = [&](int buf) {
        #pragma unroll
        for (int rep = 0; rep < 2; rep++) {
            int id = tid + rep * 256;
            int row = id >> 2;
            int kq = (id & 3) << 2;
            As[buf][kq + 0][row] = ra[rep].x;
            As[buf][kq + 1][row] = ra[rep].y;
            As[buf][kq + 2][row] = ra[rep].z;
            As[buf][kq + 3][row] = ra[rep].w;
        }
    };
    auto ldB = [&](int k0) {
        #pragma unroll
        for (int rep = 0; rep < 2; rep++) {
            int id = tid + rep * 256;
            if (!BT) {
                int kk = id >> 5;
                int n4 = id & 31;
                rb[rep] = *(const float4*)(B + (size_t)(k0 + kk) * N + n0 + n4 * 4);
            } else {
                int n = id >> 2;
                int kq = (id & 3) << 2;
                rb[rep] = *(const float4*)(B + (size_t)(n0 + n) * K + k0 + kq);
            }
        }
    };
    auto stB = [&](int buf) {
        #pragma unroll
        for (int rep = 0; rep < 2; rep++) {
            int id = tid + rep * 256;
            if (!BT) {
                int kk = id >> 5;
                int n4 = id & 31;
                *(float4*)&Bs[buf][kk][n4 * 4] = rb[rep];
            } else {
                int n = id >> 2;
                int kq = (id & 3) << 2;
                Bs[buf][kq + 0][n] = rb[rep].x;
                Bs[buf][kq + 1][n] = rb[rep].y;
                Bs[buf][kq + 2][n] = rb[rep].z;
                Bs[buf][kq + 3][n] = rb[rep].w;
            }
        }
    };

    int nt = K >> 4;
    ldA(0); ldB(0);
    stA(0); stB(0);
    __syncthreads();

    for (int t = 0; t < nt; t++) {
        int cur = t & 1;
        if (t + 1 < nt) { ldA((t + 1) << 4); ldB((t + 1) << 4); }
        #pragma unroll
        for (int k = 0; k < 16; k++) {
            float a[8], b[8];
            *(float4*)&a[0] = *(const float4*)&As[cur][k][ty * 8];
            *(float4*)&a[4] = *(const float4*)&As[cur][k][ty * 8 + 4];
            *(float4*)&b[0] = *(const float4*)&Bs[cur][k][tx * 8];
            *(float4*)&b[4] = *(const float4*)&Bs[cur][k][tx * 8 + 4];
            #pragma unroll
            for (int i = 0; i < 8; i++)
                #pragma unroll
                for (int j = 0; j < 8; j++)
                    acc[i][j] += a[i] * b[j];
        }
        if (t + 1 < nt) {
            stA(cur ^ 1); stB(cur ^ 1);
            __syncthreads();
        }
    }

    float bv[8];
    *(float4*)&bv[0] = *(const float4*)&bias[n0 + tx * 8];
    *(float4*)&bv[4] = *(const float4*)&bias[n0 + tx * 8 + 4];

    if (!LNOUT) {
        #pragma unroll
        for (int i = 0; i < 8; i++) {
            int gr = m0 + ty * 8 + i;
            if (gr < M) {
                float4 o0 = make_float4(acc[i][0] + bv[0], acc[i][1] + bv[1],
                                        acc[i][2] + bv[2], acc[i][3] + bv[3]);
                float4 o1 = make_float4(acc[i][4] + bv[4], acc[i][5] + bv[5],
                                        acc[i][6] + bv[6], acc[i][7] + bv[7]);
                *(float4*)(C + (size_t)gr * N + n0 + tx * 8)     = o0;
                *(float4*)(C + (size_t)gr * N + n0 + tx * 8 + 4) = o1;
            }
        }
    } else {
        // fused LN(128)+relu over the full row (held by 16 threads sharing ty)
        float gg[8], bb[8];
        *(float4*)&gg[0] = *(const float4*)&lnG[tx * 8];
        *(float4*)&gg[4] = *(const float4*)&lnG[tx * 8 + 4];
        *(float4*)&bb[0] = *(const float4*)&lnB[tx * 8];
        *(float4*)&bb[4] = *(const float4*)&lnB[tx * 8 + 4];
        #pragma unroll
        for (int i = 0; i < 8; i++) {
            int gr = m0 + ty * 8 + i;
            float pre[8];
            float s = 0.f;
            #pragma unroll
            for (int j = 0; j < 8; j++) { pre[j] = acc[i][j] + bv[j]; s += pre[j]; }
            s = warpSum16(s);
            float mu = s * (1.f / 128.f);
            float q = 0.f;
            #pragma unroll
            for (int j = 0; j < 8; j++) { float d = pre[j] - mu; q += d * d; }
            q = warpSum16(q);
            float rstd = rsqrtf(q * (1.f / 128.f) + LNEPS);
            if (gr < M) {
                float o[8];
                #pragma unroll
                for (int j = 0; j < 8; j++)
                    o[j] = fmaxf((pre[j] - mu) * rstd * gg[j] + bb[j], 0.f);
                *(float4*)(C + (size_t)gr * N + tx * 8)     = *(float4*)&o[0];
                *(float4*)(C + (size_t)gr * N + tx * 8 + 4) = *(float4*)&o[4];
            }
        }
    }
}

// ---------------- merged edge attention: logit + exp + segment sum ----------------
// softmax is shift-invariant; logits = relu(..) in [0, ~6], so exp() is safe
// without the segment-max subtraction.
__global__ void k_eatt(const int* __restrict__ src, const int* __restrict__ dst,
                       const float* __restrict__ b_edge, int E)
{
    int e = blockIdx.x * blockDim.x + threadIdx.x;
    if (e >= E) return;
    int dv = dst[e];
    float l = fmaxf(g_pd[dv] + g_ps[src[e]] + b_edge[0], 0.f);
    float a = expf(l);
    g_aexp[e] = a;
    atomicAdd(&g_asum[dv], a);
}

__global__ __launch_bounds__(256) void k_ectx(const int* __restrict__ src,
                                              const int* __restrict__ dst, int E)
{
    int e = blockIdx.x * 8 + (threadIdx.x >> 5);
    if (e >= E) return;
    int lane = threadIdx.x & 31;
    int s = src[e], dv = dst[e];
    float w = g_aexp[e] / g_asum[dv];
    float4 h = *(const float4*)&g_hv[(size_t)s * DV + lane * 4];
    float* c = &g_ctx[(size_t)dv * DV + lane * 4];
    red4(c, w * h.x, w * h.y, w * h.z, w * h.w);
}

// ---------------- fused kron edge GEMM + LN + relu + scatter (R12-proven) --------
__global__ __launch_bounds__(256) void k_kron(
    const int* __restrict__ src, const int* __restrict__ dst,
    const float* __restrict__ Wk2, const float* __restrict__ bk2,
    const float* __restrict__ g2, const float* __restrict__ beta2, int E)
{
    __shared__ float a_s[64][KP];
    __shared__ float b_s[64][KP];
    __shared__ int dst_s[64];
    int tid = threadIdx.x;
    int e0 = blockIdx.x * 64;

    for (int idx = tid; idx < 64 * KP; idx += 256) {
        int e = idx / KP, c = idx % KP;
        int ge = e0 + e;
        float av = 0.f, bv = 0.f;
        if (ge < E) {
            av = g_npj[(size_t)src[ge] * KP + c];
            bv = g_npj[(size_t)dst[ge] * KP + c];
        }
        a_s[e][c] = av;
        b_s[e][c] = bv;
    }
    if (tid < 64) dst_s[tid] = (e0 + tid < E) ? dst[e0 + tid] : 0;
    __syncthreads();

    int ot = tid & 15;
    int et = tid >> 4;

    u64 acc2[4][4] = {};

    for (int i = 0; i < KP; i++) {
        float a0 = a_s[et * 4 + 0][i];
        float a1 = a_s[et * 4 + 1][i];
        float a2 = a_s[et * 4 + 2][i];
        float a3 = a_s[et * 4 + 3][i];
        #pragma unroll 4
        for (int j = 0; j < KP; j++) {
            int k = i * KP + j;
            const double2* wp = (const double2*)(Wk2 + (size_t)k * NOUT + ot * 8);
            double2 wA = wp[0], wB = wp[1];
            u64 w2[4] = { dl(wA.x), dl(wA.y), dl(wB.x), dl(wB.y) };
            u64 t0 = bcast2(a0 * b_s[et * 4 + 0][j]);
            u64 t1 = bcast2(a1 * b_s[et * 4 + 1][j]);
            u64 t2 = bcast2(a2 * b_s[et * 4 + 2][j]);
            u64 t3 = bcast2(a3 * b_s[et * 4 + 3][j]);
            #pragma unroll
            for (int c = 0; c < 4; c++) {
                fma2(acc2[0][c], t0, w2[c]);
                fma2(acc2[1][c], t1, w2[c]);
                fma2(acc2[2][c], t2, w2[c]);
                fma2(acc2[3][c], t3, w2[c]);
            }
        }
    }

    float bk[8], gg[8], bb[8];
    *(float4*)&bk[0] = *(const float4*)&bk2[ot * 8];
    *(float4*)&bk[4] = *(const float4*)&bk2[ot * 8 + 4];
    *(float4*)&gg[0] = *(const float4*)&g2[ot * 8];
    *(float4*)&gg[4] = *(const float4*)&g2[ot * 8 + 4];
    *(float4*)&bb[0] = *(const float4*)&beta2[ot * 8];
    *(float4*)&bb[4] = *(const float4*)&beta2[ot * 8 + 4];

    #pragma unroll
    for (int e = 0; e < 4; e++) {
        int le = et * 4 + e;
        int ge = e0 + le;
        float pre[8];
        float s = 0.f;
        #pragma unroll
        for (int c = 0; c < 4; c++) {
            float2 p = unpack2(acc2[e][c]);
            pre[c * 2]     = p.x + bk[c * 2];
            pre[c * 2 + 1] = p.y + bk[c * 2 + 1];
            s += pre[c * 2] + pre[c * 2 + 1];
        }
        s = warpSum16(s);
        float mu = s * (1.f / NOUT);
        float q = 0.f;
        #pragma unroll
        for (int c = 0; c < 8; c++) { float d = pre[c] - mu; q += d * d; }
        q = warpSum16(q);
        float rstd = rsqrtf(q * (1.f / NOUT) + LNEPS);
        if (ge < E) {
            float* outp = &g_kron[(size_t)dst_s[le] * NOUT + ot * 8];
            float y[8];
            #pragma unroll
            for (int c = 0; c < 8; c++)
                y[c] = fmaxf((pre[c] - mu) * rstd * gg[c] + bb[c], 0.f);
            red4(outp,     y[0], y[1], y[2], y[3]);
            red4(outp + 4, y[4], y[5], y[6], y[7]);
        }
    }
}

// ---------------- GRU combine + relu + LN(128) ----------------
__global__ __launch_bounds__(128) void k_gru(const float* __restrict__ nf,
                                             const float* __restrict__ lng,
                                             const float* __restrict__ lnb, int V)
{
    int v = blockIdx.x;
    int d = threadIdx.x;
    int wid = d >> 5, lane = d & 31;
    const float* gi = g_gi + (size_t)v * 3 * DV;
    const float* gh = g_gh + (size_t)v * 3 * DV;
    float r = 1.f / (1.f + expf(-(gi[d] + gh[d])));
    float z = 1.f / (1.f + expf(-(gi[DV + d] + gh[DV + d])));
    float nn = tanhf(gi[2 * DV + d] + r * gh[2 * DV + d]);
    float h = (1.f - z) * nn + z * nf[(size_t)v * DV + d];
    float x = fmaxf(h, 0.f);

    __shared__ float red[4];
    float s = warpSum32(x);
    if (lane == 0) red[wid] = s;
    __syncthreads();
    float mu = (red[0] + red[1] + red[2] + red[3]) * (1.f / DV);
    __syncthreads();
    float c = x - mu;
    float q = warpSum32(c * c);
    if (lane == 0) red[wid] = q;
    __syncthreads();
    float var = (red[0] + red[1] + red[2] + red[3]) * (1.f / DV);
    g_gru[(size_t)v * DV + d] = c * rsqrtf(var + LNEPS) * lng[d] + lnb[d];
}

// ---------------- host ----------------
static inline int cdiv(int a, int b) { return (a + b - 1) / b; }

extern "C" void kernel_launch(void* const* d_in, const int* in_sizes, int n_in,
                              void* d_out, int out_size)
{
    const float* nf     = (const float*)d_in[0];
    const int*   src    = (const int*)d_in[1];
    const int*   dst    = (const int*)d_in[2];
    const float* W_edge = (const float*)d_in[3];
    const float* b_edge = (const float*)d_in[4];
    const float* W_pn   = (const float*)d_in[5];
    const float* b_pn   = (const float*)d_in[6];
    const float* W_ih   = (const float*)d_in[7];
    const float* b_ih   = (const float*)d_in[8];
    const float* W_hh   = (const float*)d_in[9];
    const float* b_hh   = (const float*)d_in[10];
    const float* ln_g   = (const float*)d_in[11];
    const float* ln_b   = (const float*)d_in[12];
    const float* Wk1    = (const float*)d_in[13];
    const float* bk1    = (const float*)d_in[14];
    const float* lnk1_g = (const float*)d_in[15];
    const float* lnk1_b = (const float*)d_in[16];
    const float* Wk2    = (const float*)d_in[17];
    const float* bk2    = (const float*)d_in[18];
    const float* lnk2_g = (const float*)d_in[19];
    const float* lnk2_b = (const float*)d_in[20];
    const float* Wc     = (const float*)d_in[21];
    const float* bc     = (const float*)d_in[22];
    const float* lnc_g  = (const float*)d_in[23];
    const float* lnc_b  = (const float*)d_in[24];
    float* out = (float*)d_out;

    int V = in_sizes[0] / DV;
    int E = in_sizes[1];

    float *p_hv, *p_gh, *p_gi, *p_ctx, *p_gru, *p_kron;
    cudaGetSymbolAddress((void**)&p_hv,   g_hv);
    cudaGetSymbolAddress((void**)&p_gh,   g_gh);
    cudaGetSymbolAddress((void**)&p_gi,   g_gi);
    cudaGetSymbolAddress((void**)&p_ctx,  g_ctx);
    cudaGetSymbolAddress((void**)&p_gru,  g_gru);
    cudaGetSymbolAddress((void**)&p_kron, g_kron);

    k_zero<<<cdiv(V * DV, 256), 256>>>(V);
    k_node_pre<<<cdiv(V, 8), 256>>>(nf, Wk1, bk1, lnk1_g, lnk1_b, W_edge, V);

    // hv = nf @ W_pn + b_pn
    sgemm<false, false, false><<<dim3(cdiv(V, 128), 1), 256>>>(
        nf, nf, DV, W_pn, b_pn, p_hv, V, DV, DV, nullptr, nullptr);
    // gh = nf @ W_hh^T + b_hh
    sgemm<true, false, false><<<dim3(cdiv(V, 128), 3), 256>>>(
        nf, nf, DV, W_hh, b_hh, p_gh, V, 3 * DV, DV, nullptr, nullptr);

    k_eatt<<<cdiv(E, 256), 256>>>(src, dst, b_edge, E);
    k_ectx<<<cdiv(E, 8), 256>>>(src, dst, E);

    k_kron<<<cdiv(E, 64), 256>>>(src, dst, Wk2, bk2, lnk2_g, lnk2_b, E);

    // gi = relu(context) @ W_ih^T + b_ih
    sgemm<true, true, false><<<dim3(cdiv(V, 128), 3), 256>>>(
        p_ctx, p_ctx, DV, W_ih, b_ih, p_gi, V, 3 * DV, DV, nullptr, nullptr);

    k_gru<<<V, 128>>>(nf, ln_g, ln_b, V);

    // out = relu(LN([gru, kron] @ Wc + bc))  -- fused epilogue, writes d_out
    sgemm<false, false, true><<<dim3(cdiv(V, 128), 1), 256>>>(
        p_gru, p_kron, DV, Wc, bc, out, V, DV, 2 * DV, lnc_g, lnc_b);
}

// round 15
// speedup vs baseline: 14.5137x; 1.4801x over previous
#include <cuda_runtime.h>
#include <cuda_bf16.h>
#include <math.h>

#define DV   128
#define KP   20
#define NOUT 128
#define LNEPS 1e-5f

constexpr int VMAX = 100000;
constexpr int EMAX = 400000;
constexpr int KPAD = 416;   // 400 padded to 13*32
constexpr int NCHUNK = 13;
constexpr int CH = 32;      // k per chunk (bf16)

typedef unsigned long long u64;
typedef unsigned int u32;

// ---------------- scratch (device globals; no allocation allowed) ----------------
__device__ float g_npj[VMAX * KP];
__device__ float g_pd[VMAX];
__device__ float g_ps[VMAX];
__device__ float g_hv[VMAX * DV];
__device__ float g_gh[VMAX * 3 * DV];
__device__ float g_gi[VMAX * 3 * DV];
__device__ float g_asum[VMAX];
__device__ float g_aexp[EMAX];
__device__ float g_ctx[VMAX * DV];
__device__ float g_kron[VMAX * NOUT];
__device__ float g_gru[VMAX * DV];
// Wk2^T as bf16 hi/lo: [n=128][k=KPAD] row-major
__device__ __nv_bfloat16 g_wbh[128 * KPAD];
__device__ __nv_bfloat16 g_wbl[128 * KPAD];

// ---------------- helpers ----------------
__device__ __forceinline__ void red4(float* p, float x, float y, float z, float w) {
    asm volatile("red.global.add.v4.f32 [%0], {%1, %2, %3, %4};"
                 :: "l"(p), "f"(x), "f"(y), "f"(z), "f"(w) : "memory");
}
__device__ __forceinline__ void red2(float* p, float x, float y) {
    asm volatile("red.global.add.v2.f32 [%0], {%1, %2};"
                 :: "l"(p), "f"(x), "f"(y) : "memory");
}
__device__ __forceinline__ float warpSum32(float v) {
    #pragma unroll
    for (int m = 16; m > 0; m >>= 1) v += __shfl_xor_sync(0xffffffffu, v, m);
    return v;
}
__device__ __forceinline__ float warpSum16(float v) {
    #pragma unroll
    for (int m = 8; m > 0; m >>= 1) v += __shfl_xor_sync(0xffffffffu, v, m);
    return v;
}
__device__ __forceinline__ u32 smem_u32(const void* p) {
    u32 a;
    asm("{ .reg .u64 t; cvta.to.shared.u64 t, %1; cvt.u32.u64 %0, t; }" : "=r"(a) : "l"(p));
    return a;
}
__device__ __forceinline__ void ldsm4(u32* r, u32 addr) {
    asm volatile("ldmatrix.sync.aligned.m8n8.x4.shared.b16 {%0,%1,%2,%3}, [%4];"
                 : "=r"(r[0]), "=r"(r[1]), "=r"(r[2]), "=r"(r[3]) : "r"(addr));
}
__device__ __forceinline__ void ldsm2(u32* r, u32 addr) {
    asm volatile("ldmatrix.sync.aligned.m8n8.x2.shared.b16 {%0,%1}, [%2];"
                 : "=r"(r[0]), "=r"(r[1]) : "r"(addr));
}
__device__ __forceinline__ void mma16816(float* c, const u32* a, const u32* b) {
    asm volatile("mma.sync.aligned.m16n8k16.row.col.f32.bf16.bf16.f32 "
                 "{%0,%1,%2,%3}, {%4,%5,%6,%7}, {%8,%9}, {%0,%1,%2,%3};"
                 : "+f"(c[0]), "+f"(c[1]), "+f"(c[2]), "+f"(c[3])
                 : "r"(a[0]), "r"(a[1]), "r"(a[2]), "r"(a[3]), "r"(b[0]), "r"(b[1]));
}

// ---------------- zero init ----------------
__global__ void k_zero(int V) {
    int i = blockIdx.x * blockDim.x + threadIdx.x;
    int n = V * DV;
    if (i < n) { g_ctx[i] = 0.f; g_kron[i] = 0.f; }
    if (i < V) { g_asum[i] = 0.f; }
}

// ---------------- Wk2^T -> bf16 hi/lo [128][KPAD] ----------------
__global__ void k_wconv(const float* __restrict__ Wk2) {
    int idx = blockIdx.x * blockDim.x + threadIdx.x;
    if (idx >= 128 * KPAD) return;
    int n = idx / KPAD;
    int k = idx - n * KPAD;
    float v = (k < KP * KP) ? Wk2[(size_t)k * NOUT + n] : 0.f;
    __nv_bfloat16 hi = __float2bfloat16(v);
    __nv_bfloat16 lo = __float2bfloat16(v - __bfloat162float(hi));
    g_wbh[idx] = hi;
    g_wbl[idx] = lo;
}

// ---------------- per-node precompute: npj (LN+relu over 20), pd, ps ----------------
__global__ __launch_bounds__(256) void k_node_pre(
    const float* __restrict__ nf, const float* __restrict__ Wk1,
    const float* __restrict__ bk1, const float* __restrict__ g1,
    const float* __restrict__ b1, const float* __restrict__ W_edge, int V)
{
    __shared__ __align__(16) float nfs[8][DV];
    int w = threadIdx.x >> 5, lane = threadIdx.x & 31;
    int v = blockIdx.x * 8 + w;
    if (v < V) {
        float4 t = *(const float4*)&nf[(size_t)v * DV + lane * 4];
        *(float4*)&nfs[w][lane * 4] = t;
    }
    __syncwarp();
    if (v >= V) return;

    const float* base;
    int stride;
    if (lane < KP)       { base = Wk1 + lane;     stride = KP; }
    else if (lane == 20) { base = W_edge;         stride = 1;  }
    else if (lane == 21) { base = W_edge + DV;    stride = 1;  }
    else                 { base = W_edge;         stride = 0;  }

    float acc = 0.f;
    #pragma unroll 8
    for (int k = 0; k < DV; k++) acc += nfs[w][k] * base[(size_t)k * stride];

    float x = (lane < KP) ? acc + bk1[lane] : 0.f;
    float s = warpSum32((lane < KP) ? x : 0.f);
    float mu = s * (1.f / KP);
    float c = (lane < KP) ? (x - mu) : 0.f;
    float q = warpSum32(c * c);
    float rstd = rsqrtf(q * (1.f / KP) + LNEPS);
    if (lane < KP) {
        g_npj[(size_t)v * KP + lane] = fmaxf(c * rstd * g1[lane] + b1[lane], 0.f);
    } else if (lane == 20) {
        g_pd[v] = acc;
    } else if (lane == 21) {
        g_ps[v] = acc;
    }
}

// ---------------- double-buffered tiled SGEMM (R13-proven) ----------------
template<bool BT, bool RA, bool LNOUT>
__global__ __launch_bounds__(256, 2) void sgemm(
    const float* __restrict__ A1, const float* __restrict__ A2, int kSplit,
    const float* __restrict__ B, const float* __restrict__ bias,
    float* __restrict__ C, int M, int N, int K,
    const float* __restrict__ lnG, const float* __restrict__ lnB)
{
    __shared__ __align__(16) float As[2][16][128];
    __shared__ __align__(16) float Bs[2][16][128];
    int tid = threadIdx.x;
    int m0 = blockIdx.x * 128;
    int n0 = blockIdx.y * 128;
    int tx = tid & 15;
    int ty = tid >> 4;

    float acc[8][8];
    #pragma unroll
    for (int i = 0; i < 8; i++)
        #pragma unroll
        for (int j = 0; j < 8; j++) acc[i][j] = 0.f;

    float4 ra[2], rb[2];

    auto ldA = [&](int k0) {
        #pragma unroll
        for (int rep = 0; rep < 2; rep++) {
            int id = tid + rep * 256;
            int row = id >> 2;
            int kq = (id & 3) << 2;
            int gr = m0 + row;
            int kk = k0 + kq;
            float4 v = make_float4(0.f, 0.f, 0.f, 0.f);
            if (gr < M) {
                if (kk < kSplit) v = *(const float4*)(A1 + (size_t)gr * kSplit + kk);
                else             v = *(const float4*)(A2 + (size_t)gr * (K - kSplit) + (kk - kSplit));
            }
            if (RA) {
                v.x = fmaxf(v.x, 0.f); v.y = fmaxf(v.y, 0.f);
                v.z = fmaxf(v.z, 0.f); v.w = fmaxf(v.w, 0.f);
            }
            ra[rep] = v;
        }
    };
    auto stA = [&](int buf) {
        #pragma unroll
        for (int rep = 0; rep < 2; rep++) {
            int id = tid + rep * 256;
            int row = id >> 2;
            int kq = (id & 3) << 2;
            As[buf][kq + 0][row] = ra[rep].x;
            As[buf][kq + 1][row] = ra[rep].y;
            As[buf][kq + 2][row] = ra[rep].z;
            As[buf][kq + 3][row] = ra[rep].w;
        }
    };
    auto ldB = [&](int k0) {
        #pragma unroll
        for (int rep = 0; rep < 2; rep++) {
            int id = tid + rep * 256;
            if (!BT) {
                int kk = id >> 5;
                int n4 = id & 31;
                rb[rep] = *(const float4*)(B + (size_t)(k0 + kk) * N + n0 + n4 * 4);
            } else {
                int n = id >> 2;
                int kq = (id & 3) << 2;
                rb[rep] = *(const float4*)(B + (size_t)(n0 + n) * K + k0 + kq);
            }
        }
    };
    auto stB = [&](int buf) {
        #pragma unroll
        for (int rep = 0; rep < 2; rep++) {
            int id = tid + rep * 256;
            if (!BT) {
                int kk = id >> 5;
                int n4 = id & 31;
                *(float4*)&Bs[buf][kk][n4 * 4] = rb[rep];
            } else {
                int n = id >> 2;
                int kq = (id & 3) << 2;
                Bs[buf][kq + 0][n] = rb[rep].x;
                Bs[buf][kq + 1][n] = rb[rep].y;
                Bs[buf][kq + 2][n] = rb[rep].z;
                Bs[buf][kq + 3][n] = rb[rep].w;
            }
        }
    };

    int nt = K >> 4;
    ldA(0); ldB(0);
    stA(0); stB(0);
    __syncthreads();

    for (int t = 0; t < nt; t++) {
        int cur = t & 1;
        if (t + 1 < nt) { ldA((t + 1) << 4); ldB((t + 1) << 4); }
        #pragma unroll
        for (int k = 0; k < 16; k++) {
            float a[8], b[8];
            *(float4*)&a[0] = *(const float4*)&As[cur][k][ty * 8];
            *(float4*)&a[4] = *(const float4*)&As[cur][k][ty * 8 + 4];
            *(float4*)&b[0] = *(const float4*)&Bs[cur][k][tx * 8];
            *(float4*)&b[4] = *(const float4*)&Bs[cur][k][tx * 8 + 4];
            #pragma unroll
            for (int i = 0; i < 8; i++)
                #pragma unroll
                for (int j = 0; j < 8; j++)
                    acc[i][j] += a[i] * b[j];
        }
        if (t + 1 < nt) {
            stA(cur ^ 1); stB(cur ^ 1);
            __syncthreads();
        }
    }

    float bv[8];
    *(float4*)&bv[0] = *(const float4*)&bias[n0 + tx * 8];
    *(float4*)&bv[4] = *(const float4*)&bias[n0 + tx * 8 + 4];

    if (!LNOUT) {
        #pragma unroll
        for (int i = 0; i < 8; i++) {
            int gr = m0 + ty * 8 + i;
            if (gr < M) {
                float4 o0 = make_float4(acc[i][0] + bv[0], acc[i][1] + bv[1],
                                        acc[i][2] + bv[2], acc[i][3] + bv[3]);
                float4 o1 = make_float4(acc[i][4] + bv[4], acc[i][5] + bv[5],
                                        acc[i][6] + bv[6], acc[i][7] + bv[7]);
                *(float4*)(C + (size_t)gr * N + n0 + tx * 8)     = o0;
                *(float4*)(C + (size_t)gr * N + n0 + tx * 8 + 4) = o1;
            }
        }
    } else {
        float gg[8], bb[8];
        *(float4*)&gg[0] = *(const float4*)&lnG[tx * 8];
        *(float4*)&gg[4] = *(const float4*)&lnG[tx * 8 + 4];
        *(float4*)&bb[0] = *(const float4*)&lnB[tx * 8];
        *(float4*)&bb[4] = *(const float4*)&lnB[tx * 8 + 4];
        #pragma unroll
        for (int i = 0; i < 8; i++) {
            int gr = m0 + ty * 8 + i;
            float pre[8];
            float s = 0.f;
            #pragma unroll
            for (int j = 0; j < 8; j++) { pre[j] = acc[i][j] + bv[j]; s += pre[j]; }
            s = warpSum16(s);
            float mu = s * (1.f / 128.f);
            float q = 0.f;
            #pragma unroll
            for (int j = 0; j < 8; j++) { float d = pre[j] - mu; q += d * d; }
            q = warpSum16(q);
            float rstd = rsqrtf(q * (1.f / 128.f) + LNEPS);
            if (gr < M) {
                float o[8];
                #pragma unroll
                for (int j = 0; j < 8; j++)
                    o[j] = fmaxf((pre[j] - mu) * rstd * gg[j] + bb[j], 0.f);
                *(float4*)(C + (size_t)gr * N + tx * 8)     = *(float4*)&o[0];
                *(float4*)(C + (size_t)gr * N + tx * 8 + 4) = *(float4*)&o[4];
            }
        }
    }
}

// ---------------- merged edge attention ----------------
__global__ void k_eatt(const int* __restrict__ src, const int* __restrict__ dst,
                       const float* __restrict__ b_edge, int E)
{
    int e = blockIdx.x * blockDim.x + threadIdx.x;
    if (e >= E) return;
    int dv = dst[e];
    float l = fmaxf(g_pd[dv] + g_ps[src[e]] + b_edge[0], 0.f);
    float a = expf(l);
    g_aexp[e] = a;
    atomicAdd(&g_asum[dv], a);
}

__global__ __launch_bounds__(256) void k_ectx(const int* __restrict__ src,
                                              const int* __restrict__ dst, int E)
{
    int e = blockIdx.x * 8 + (threadIdx.x >> 5);
    if (e >= E) return;
    int lane = threadIdx.x & 31;
    int s = src[e], dv = dst[e];
    float w = g_aexp[e] / g_asum[dv];
    float4 h = *(const float4*)&g_hv[(size_t)s * DV + lane * 4];
    float* c = &g_ctx[(size_t)dv * DV + lane * 4];
    red4(c, w * h.x, w * h.y, w * h.z, w * h.w);
}

// ---------------- mma.sync kron: bf16x3 HMMA + LN + relu + scatter ----------------
// CTA = 128 edges x 128 cols. 8 warps: rg=wid&3 (32 rows), chf=wid>>2 (64-col half).
// Warp tile 32x64 via m16n8k16: 2 m-tiles x 8 n-tiles, 3 split MMAs each.
// smem (bytes): A_hi 0, A_lo 10240, B_hi 20480, B_lo 30720 (each 128 rows x 40 bf16),
//               npa 40960, npb 51200 ([128][20] f32), dst 61440, prm 61952, red 63488.
#define SA_HI 0
#define SA_LO 10240
#define SB_HI 20480
#define SB_LO 30720
#define S_NPA 40960
#define S_NPB 51200
#define S_DST 61440
#define S_PRM 61952
#define S_RED 63488
#define KRON_SMEM 65536
#define ROWB 80   // smem row stride in bytes (40 bf16)

__global__ __launch_bounds__(256, 2) void k_kron_mma(
    const int* __restrict__ src, const int* __restrict__ dst,
    const float* __restrict__ bk2,
    const float* __restrict__ g2, const float* __restrict__ beta2, int E)
{
    extern __shared__ __align__(16) char sm[];
    u32 smb = smem_u32(sm);
    int tid = threadIdx.x;
    int wid = tid >> 5;
    int lane = tid & 31;
    int e0 = blockIdx.x * 128;
    int rg = wid & 3;
    int chf = wid >> 2;

    float* npa = (float*)(sm + S_NPA);
    float* npb = (float*)(sm + S_NPB);
    int* dst_s = (int*)(sm + S_DST);
    float* prm = (float*)(sm + S_PRM);
    float2* redb = (float2*)(sm + S_RED);

    // stage npj rows + params
    for (int idx = tid; idx < 128 * KP; idx += 256) {
        int e = idx / KP, c = idx - e * KP;
        int ge = e0 + e;
        float av = 0.f, bv = 0.f;
        if (ge < E) {
            av = g_npj[(size_t)src[ge] * KP + c];
            bv = g_npj[(size_t)dst[ge] * KP + c];
        }
        npa[e * KP + c] = av;
        npb[e * KP + c] = bv;
    }
    if (tid < 128) {
        dst_s[tid] = (e0 + tid < E) ? dst[e0 + tid] : 0;
        prm[tid] = bk2[tid];
        prm[128 + tid] = g2[tid];
        prm[256 + tid] = beta2[tid];
    }
    __syncthreads();

    float c[2][8][4];
    #pragma unroll
    for (int mt = 0; mt < 2; mt++)
        #pragma unroll
        for (int nt = 0; nt < 8; nt++)
            #pragma unroll
            for (int q = 0; q < 4; q++) c[mt][nt][q] = 0.f;

    int arow = tid >> 1;
    int akh = (tid & 1) * 16;
    const float* ar = npa + arow * KP;
    const float* br = npb + arow * KP;

    for (int ch = 0; ch < NCHUNK; ch++) {
        // ---- build A chunk: 16 kron values per thread -> bf16 hi/lo ----
        {
            u32 hw[8], lw[8];
            #pragma unroll
            for (int t4 = 0; t4 < 8; t4++) {
                u32 h2 = 0, l2 = 0;
                #pragma unroll
                for (int u = 0; u < 2; u++) {
                    int kk = ch * CH + akh + t4 * 2 + u;
                    float v = 0.f;
                    if (kk < KP * KP) {
                        int i = kk / KP;
                        int j = kk - i * KP;
                        v = ar[i] * br[j];
                    }
                    __nv_bfloat16 h = __float2bfloat16(v);
                    __nv_bfloat16 l = __float2bfloat16(v - __bfloat162float(h));
                    h2 |= (u32)__bfloat16_as_ushort(h) << (16 * u);
                    l2 |= (u32)__bfloat16_as_ushort(l) << (16 * u);
                }
                hw[t4] = h2; lw[t4] = l2;
            }
            char* pa = sm + SA_HI + arow * ROWB + akh * 2;
            char* pl = sm + SA_LO + arow * ROWB + akh * 2;
            *(uint4*)pa = *(uint4*)&hw[0];
            *(uint4*)(pa + 16) = *(uint4*)&hw[4];
            *(uint4*)pl = *(uint4*)&lw[0];
            *(uint4*)(pl + 16) = *(uint4*)&lw[4];
        }
        // ---- copy B chunk from global bf16 [128][KPAD] ----
        #pragma unroll
        for (int rep = 0; rep < 2; rep++) {
            int i = tid + rep * 256;       // 0..511 uint4
            int row = i >> 2;
            int q = i & 3;
            const uint4* srch = (const uint4*)(g_wbh + row * KPAD + ch * CH + q * 8);
            const uint4* srcl = (const uint4*)(g_wbl + row * KPAD + ch * CH + q * 8);
            *(uint4*)(sm + SB_HI + row * ROWB + q * 16) = *srch;
            *(uint4*)(sm + SB_LO + row * ROWB + q * 16) = *srcl;
        }
        __syncthreads();

        // ---- MMA ----
        #pragma unroll
        for (int ks = 0; ks < 2; ks++) {
            u32 ah[2][4], al[2][4];
            #pragma unroll
            for (int mt = 0; mt < 2; mt++) {
                u32 abase = smb + SA_HI
                          + (u32)(rg * 32 + mt * 16 + (lane & 15)) * ROWB
                          + (u32)(ks * 16 + (lane >> 4) * 8) * 2;
                ldsm4(ah[mt], abase);
                ldsm4(al[mt], abase + (SA_LO - SA_HI));
            }
            #pragma unroll
            for (int nt = 0; nt < 8; nt++) {
                u32 bbase = smb + SB_HI
                          + (u32)(chf * 64 + nt * 8 + (lane & 7)) * ROWB
                          + (u32)(ks * 16 + ((lane >> 3) & 1) * 8) * 2;
                u32 bh[2], bl[2];
                ldsm2(bh, bbase);
                ldsm2(bl, bbase + (SB_LO - SB_HI));
                #pragma unroll
                for (int mt = 0; mt < 2; mt++) {
                    mma16816(c[mt][nt], ah[mt], bh);
                    mma16816(c[mt][nt], ah[mt], bl);
                    mma16816(c[mt][nt], al[mt], bh);
                }
            }
        }
        __syncthreads();
    }

    // ---- epilogue: bias + LN(128) + relu + red2 scatter ----
    int quad = lane >> 2;
    int qlan = lane & 3;

    #pragma unroll
    for (int mt = 0; mt < 2; mt++) {
        int rl = rg * 32 + mt * 16 + quad;
        int rh = rl + 8;
        float sl = 0.f, ql = 0.f, sh = 0.f, qh = 0.f;
        #pragma unroll
        for (int nt = 0; nt < 8; nt++) {
            int col = chf * 64 + nt * 8 + qlan * 2;
            float p0 = c[mt][nt][0] + prm[col];
            float p1 = c[mt][nt][1] + prm[col + 1];
            float p2 = c[mt][nt][2] + prm[col];
            float p3 = c[mt][nt][3] + prm[col + 1];
            sl += p0 + p1; ql += p0 * p0 + p1 * p1;
            sh += p2 + p3; qh += p2 * p2 + p3 * p3;
        }
        sl += __shfl_xor_sync(0xffffffffu, sl, 1); sl += __shfl_xor_sync(0xffffffffu, sl, 2);
        ql += __shfl_xor_sync(0xffffffffu, ql, 1); ql += __shfl_xor_sync(0xffffffffu, ql, 2);
        sh += __shfl_xor_sync(0xffffffffu, sh, 1); sh += __shfl_xor_sync(0xffffffffu, sh, 2);
        qh += __shfl_xor_sync(0xffffffffu, qh, 1); qh += __shfl_xor_sync(0xffffffffu, qh, 2);
        if (qlan == 0) {
            redb[rl * 2 + chf] = make_float2(sl, ql);
            redb[rh * 2 + chf] = make_float2(sh, qh);
        }
    }
    __syncthreads();

    #pragma unroll
    for (int mt = 0; mt < 2; mt++) {
        int rl = rg * 32 + mt * 16 + quad;
        int rh = rl + 8;
        float2 t0 = redb[rl * 2 + 0], t1 = redb[rl * 2 + 1];
        float mul = (t0.x + t1.x) * (1.f / NOUT);
        float rsl = rsqrtf((t0.y + t1.y) * (1.f / NOUT) - mul * mul + LNEPS);
        float2 u0 = redb[rh * 2 + 0], u1 = redb[rh * 2 + 1];
        float muh = (u0.x + u1.x) * (1.f / NOUT);
        float rsh = rsqrtf((u0.y + u1.y) * (1.f / NOUT) - muh * muh + LNEPS);
        bool okl = (e0 + rl < E);
        bool okh = (e0 + rh < E);
        float* dl = g_kron + (size_t)dst_s[rl] * NOUT;
        float* dh = g_kron + (size_t)dst_s[rh] * NOUT;
        #pragma unroll
        for (int nt = 0; nt < 8; nt++) {
            int col = chf * 64 + nt * 8 + qlan * 2;
            float gA = prm[128 + col], gB = prm[128 + col + 1];
            float bA = prm[256 + col], bB = prm[256 + col + 1];
            if (okl) {
                float y0 = fmaxf((c[mt][nt][0] + prm[col] - mul) * rsl * gA + bA, 0.f);
                float y1 = fmaxf((c[mt][nt][1] + prm[col + 1] - mul) * rsl * gB + bB, 0.f);
                red2(dl + col, y0, y1);
            }
            if (okh) {
                float y2 = fmaxf((c[mt][nt][2] + prm[col] - muh) * rsh * gA + bA, 0.f);
                float y3 = fmaxf((c[mt][nt][3] + prm[col + 1] - muh) * rsh * gB + bB, 0.f);
                red2(dh + col, y2, y3);
            }
        }
    }
}

// ---------------- GRU combine + relu + LN(128) ----------------
__global__ __launch_bounds__(128) void k_gru(const float* __restrict__ nf,
                                             const float* __restrict__ lng,
                                             const float* __restrict__ lnb, int V)
{
    int v = blockIdx.x;
    int d = threadIdx.x;
    int wid = d >> 5, lane = d & 31;
    const float* gi = g_gi + (size_t)v * 3 * DV;
    const float* gh = g_gh + (size_t)v * 3 * DV;
    float r = 1.f / (1.f + expf(-(gi[d] + gh[d])));
    float z = 1.f / (1.f + expf(-(gi[DV + d] + gh[DV + d])));
    float nn = tanhf(gi[2 * DV + d] + r * gh[2 * DV + d]);
    float h = (1.f - z) * nn + z * nf[(size_t)v * DV + d];
    float x = fmaxf(h, 0.f);

    __shared__ float red[4];
    float s = warpSum32(x);
    if (lane == 0) red[wid] = s;
    __syncthreads();
    float mu = (red[0] + red[1] + red[2] + red[3]) * (1.f / DV);
    __syncthreads();
    float c = x - mu;
    float q = warpSum32(c * c);
    if (lane == 0) red[wid] = q;
    __syncthreads();
    float var = (red[0] + red[1] + red[2] + red[3]) * (1.f / DV);
    g_gru[(size_t)v * DV + d] = c * rsqrtf(var + LNEPS) * lng[d] + lnb[d];
}

// ---------------- host ----------------
static inline int cdiv(int a, int b) { return (a + b - 1) / b; }

extern "C" void kernel_launch(void* const* d_in, const int* in_sizes, int n_in,
                              void* d_out, int out_size)
{
    const float* nf     = (const float*)d_in[0];
    const int*   src    = (const int*)d_in[1];
    const int*   dst    = (const int*)d_in[2];
    const float* W_edge = (const float*)d_in[3];
    const float* b_edge = (const float*)d_in[4];
    const float* W_pn   = (const float*)d_in[5];
    const float* b_pn   = (const float*)d_in[6];
    const float* W_ih   = (const float*)d_in[7];
    const float* b_ih   = (const float*)d_in[8];
    const float* W_hh   = (const float*)d_in[9];
    const float* b_hh   = (const float*)d_in[10];
    const float* ln_g   = (const float*)d_in[11];
    const float* ln_b   = (const float*)d_in[12];
    const float* Wk1    = (const float*)d_in[13];
    const float* bk1    = (const float*)d_in[14];
    const float* lnk1_g = (const float*)d_in[15];
    const float* lnk1_b = (const float*)d_in[16];
    const float* Wk2    = (const float*)d_in[17];
    const float* bk2    = (const float*)d_in[18];
    const float* lnk2_g = (const float*)d_in[19];
    const float* lnk2_b = (const float*)d_in[20];
    const float* Wc     = (const float*)d_in[21];
    const float* bc     = (const float*)d_in[22];
    const float* lnc_g  = (const float*)d_in[23];
    const float* lnc_b  = (const float*)d_in[24];
    float* out = (float*)d_out;

    int V = in_sizes[0] / DV;
    int E = in_sizes[1];

    float *p_hv, *p_gh, *p_gi, *p_ctx, *p_gru, *p_kron;
    cudaGetSymbolAddress((void**)&p_hv,   g_hv);
    cudaGetSymbolAddress((void**)&p_gh,   g_gh);
    cudaGetSymbolAddress((void**)&p_gi,   g_gi);
    cudaGetSymbolAddress((void**)&p_ctx,  g_ctx);
    cudaGetSymbolAddress((void**)&p_gru,  g_gru);
    cudaGetSymbolAddress((void**)&p_kron, g_kron);

    cudaFuncSetAttribute(k_kron_mma, cudaFuncAttributeMaxDynamicSharedMemorySize, KRON_SMEM);

    k_zero<<<cdiv(V * DV, 256), 256>>>(V);
    k_wconv<<<cdiv(128 * KPAD, 256), 256>>>(Wk2);
    k_node_pre<<<cdiv(V, 8), 256>>>(nf, Wk1, bk1, lnk1_g, lnk1_b, W_edge, V);

    // hv = nf @ W_pn + b_pn
    sgemm<false, false, false><<<dim3(cdiv(V, 128), 1), 256>>>(
        nf, nf, DV, W_pn, b_pn, p_hv, V, DV, DV, nullptr, nullptr);
    // gh = nf @ W_hh^T + b_hh
    sgemm<true, false, false><<<dim3(cdiv(V, 128), 3), 256>>>(
        nf, nf, DV, W_hh, b_hh, p_gh, V, 3 * DV, DV, nullptr, nullptr);

    k_eatt<<<cdiv(E, 256), 256>>>(src, dst, b_edge, E);
    k_ectx<<<cdiv(E, 8), 256>>>(src, dst, E);

    k_kron_mma<<<cdiv(E, 128), 256, KRON_SMEM>>>(src, dst, bk2, lnk2_g, lnk2_b, E);

    // gi = relu(context) @ W_ih^T + b_ih
    sgemm<true, true, false><<<dim3(cdiv(V, 128), 3), 256>>>(
        p_ctx, p_ctx, DV, W_ih, b_ih, p_gi, V, 3 * DV, DV, nullptr, nullptr);

    k_gru<<<V, 128>>>(nf, ln_g, ln_b, V);

    // out = relu(LN([gru, kron] @ Wc + bc))
    sgemm<false, false, true><<<dim3(cdiv(V, 128), 1), 256>>>(
        p_gru, p_kron, DV, Wc, bc, out, V, DV, 2 * DV, lnc_g, lnc_b);
}

// round 16
// speedup vs baseline: 16.7025x; 1.1508x over previous
#include <cuda_runtime.h>
#include <cuda_bf16.h>
#include <math.h>

#define DV   128
#define KP   20
#define NOUT 128
#define LNEPS 1e-5f

constexpr int VMAX = 100000;
constexpr int EMAX = 400000;
constexpr int KPAD = 416;   // kron K: 400 padded to 13*32
constexpr int NCHUNK = 13;
constexpr int CH = 32;

typedef unsigned long long u64;
typedef unsigned int u32;

// ---------------- scratch (device globals; no allocation allowed) ----------------
__device__ float g_npj[VMAX * KP];
__device__ float g_pd[VMAX];
__device__ float g_ps[VMAX];
__device__ float g_hv[VMAX * DV];
__device__ float g_gh[VMAX * 3 * DV];
__device__ float g_gi[VMAX * 3 * DV];
__device__ float g_asum[VMAX];
__device__ float g_aexp[EMAX];
__device__ float g_ctx[VMAX * DV];
__device__ float g_kron[VMAX * NOUT];
__device__ float g_gru[VMAX * DV];
// kron weights: Wk2^T bf16 hi/lo [128][KPAD]
__device__ __nv_bfloat16 g_wbh[128 * KPAD];
__device__ __nv_bfloat16 g_wbl[128 * KPAD];
// node GEMM A operands, bf16 hi/lo
__device__ __nv_bfloat16 g_nfh[VMAX * DV];
__device__ __nv_bfloat16 g_nfl[VMAX * DV];
__device__ __nv_bfloat16 g_cxh[VMAX * DV];
__device__ __nv_bfloat16 g_cxl[VMAX * DV];
__device__ __nv_bfloat16 g_gkh[VMAX * 2 * DV];
__device__ __nv_bfloat16 g_gkl[VMAX * 2 * DV];
// node GEMM weights [N][K] bf16 hi/lo: wpn(128x128)@0, whh(384x128)@16384,
// wih(384x128)@65536, wc(128x256)@114688; total 147456
__device__ __nv_bfloat16 g_wsh[147456];
__device__ __nv_bfloat16 g_wsl[147456];

// ---------------- helpers ----------------
__device__ __forceinline__ void red4(float* p, float x, float y, float z, float w) {
    asm volatile("red.global.add.v4.f32 [%0], {%1, %2, %3, %4};"
                 :: "l"(p), "f"(x), "f"(y), "f"(z), "f"(w) : "memory");
}
__device__ __forceinline__ void red2(float* p, float x, float y) {
    asm volatile("red.global.add.v2.f32 [%0], {%1, %2};"
                 :: "l"(p), "f"(x), "f"(y) : "memory");
}
__device__ __forceinline__ float warpSum32(float v) {
    #pragma unroll
    for (int m = 16; m > 0; m >>= 1) v += __shfl_xor_sync(0xffffffffu, v, m);
    return v;
}
__device__ __forceinline__ u32 smem_u32(const void* p) {
    u32 a;
    asm("{ .reg .u64 t; cvta.to.shared.u64 t, %1; cvt.u32.u64 %0, t; }" : "=r"(a) : "l"(p));
    return a;
}
__device__ __forceinline__ void ldsm4(u32* r, u32 addr) {
    asm volatile("ldmatrix.sync.aligned.m8n8.x4.shared.b16 {%0,%1,%2,%3}, [%4];"
                 : "=r"(r[0]), "=r"(r[1]), "=r"(r[2]), "=r"(r[3]) : "r"(addr));
}
__device__ __forceinline__ void ldsm2(u32* r, u32 addr) {
    asm volatile("ldmatrix.sync.aligned.m8n8.x2.shared.b16 {%0,%1}, [%2];"
                 : "=r"(r[0]), "=r"(r[1]) : "r"(addr));
}
__device__ __forceinline__ void mma16816(float* c, const u32* a, const u32* b) {
    asm volatile("mma.sync.aligned.m16n8k16.row.col.f32.bf16.bf16.f32 "
                 "{%0,%1,%2,%3}, {%4,%5,%6,%7}, {%8,%9}, {%0,%1,%2,%3};"
                 : "+f"(c[0]), "+f"(c[1]), "+f"(c[2]), "+f"(c[3])
                 : "r"(a[0]), "r"(a[1]), "r"(a[2]), "r"(a[3]), "r"(b[0]), "r"(b[1]));
}

// ---------------- zero / split / weight-prep kernels ----------------
__global__ void k_zero(int V) {
    int i = blockIdx.x * blockDim.x + threadIdx.x;
    int n = V * DV;
    if (i < n) { g_ctx[i] = 0.f; g_kron[i] = 0.f; }
    if (i < V) { g_asum[i] = 0.f; }
}

__global__ void k_split(const float* __restrict__ src, __nv_bfloat16* __restrict__ dh,
                        __nv_bfloat16* __restrict__ dl, int n, int relu) {
    int i = blockIdx.x * blockDim.x + threadIdx.x;
    if (i >= n) return;
    float v = src[i];
    if (relu) v = fmaxf(v, 0.f);
    __nv_bfloat16 h = __float2bfloat16(v);
    dh[i] = h;
    dl[i] = __float2bfloat16(v - __bfloat162float(h));
}

__global__ void k_split_gk(int V) {
    int i = blockIdx.x * blockDim.x + threadIdx.x;
    if (i >= V * 2 * DV) return;
    int row = i >> 8;
    int col = i & 255;
    float v = (col < DV) ? g_gru[row * DV + col] : g_kron[row * DV + col - DV];
    __nv_bfloat16 h = __float2bfloat16(v);
    g_gkh[i] = h;
    g_gkl[i] = __float2bfloat16(v - __bfloat162float(h));
}

// dest[n][k] = trans ? W[k][n] : W[n][k]
__global__ void k_wsplit(const float* __restrict__ W, __nv_bfloat16* __restrict__ dh,
                         __nv_bfloat16* __restrict__ dl, int N, int K, int trans) {
    int idx = blockIdx.x * blockDim.x + threadIdx.x;
    if (idx >= N * K) return;
    int n = idx / K;
    int k = idx - n * K;
    float v = trans ? W[(size_t)k * N + n] : W[(size_t)n * K + k];
    __nv_bfloat16 h = __float2bfloat16(v);
    dh[idx] = h;
    dl[idx] = __float2bfloat16(v - __bfloat162float(h));
}

__global__ void k_wconv(const float* __restrict__ Wk2) {
    int idx = blockIdx.x * blockDim.x + threadIdx.x;
    if (idx >= 128 * KPAD) return;
    int n = idx / KPAD;
    int k = idx - n * KPAD;
    float v = (k < KP * KP) ? Wk2[(size_t)k * NOUT + n] : 0.f;
    __nv_bfloat16 hi = __float2bfloat16(v);
    g_wbh[idx] = hi;
    g_wbl[idx] = __float2bfloat16(v - __bfloat162float(hi));
}

// ---------------- per-node precompute: npj (LN+relu over 20), pd, ps ----------------
__global__ __launch_bounds__(256) void k_node_pre(
    const float* __restrict__ nf, const float* __restrict__ Wk1,
    const float* __restrict__ bk1, const float* __restrict__ g1,
    const float* __restrict__ b1, const float* __restrict__ W_edge, int V)
{
    __shared__ __align__(16) float nfs[8][DV];
    int w = threadIdx.x >> 5, lane = threadIdx.x & 31;
    int v = blockIdx.x * 8 + w;
    if (v < V) {
        float4 t = *(const float4*)&nf[(size_t)v * DV + lane * 4];
        *(float4*)&nfs[w][lane * 4] = t;
    }
    __syncwarp();
    if (v >= V) return;

    const float* base;
    int stride;
    if (lane < KP)       { base = Wk1 + lane;     stride = KP; }
    else if (lane == 20) { base = W_edge;         stride = 1;  }
    else if (lane == 21) { base = W_edge + DV;    stride = 1;  }
    else                 { base = W_edge;         stride = 0;  }

    float acc = 0.f;
    #pragma unroll 8
    for (int k = 0; k < DV; k++) acc += nfs[w][k] * base[(size_t)k * stride];

    float x = (lane < KP) ? acc + bk1[lane] : 0.f;
    float s = warpSum32((lane < KP) ? x : 0.f);
    float mu = s * (1.f / KP);
    float c = (lane < KP) ? (x - mu) : 0.f;
    float q = warpSum32(c * c);
    float rstd = rsqrtf(q * (1.f / KP) + LNEPS);
    if (lane < KP) {
        g_npj[(size_t)v * KP + lane] = fmaxf(c * rstd * g1[lane] + b1[lane], 0.f);
    } else if (lane == 20) {
        g_pd[v] = acc;
    } else if (lane == 21) {
        g_ps[v] = acc;
    }
}

// ---------------- merged edge attention ----------------
__global__ void k_eatt(const int* __restrict__ src, const int* __restrict__ dst,
                       const float* __restrict__ b_edge, int E)
{
    int e = blockIdx.x * blockDim.x + threadIdx.x;
    if (e >= E) return;
    int dv = dst[e];
    float l = fmaxf(g_pd[dv] + g_ps[src[e]] + b_edge[0], 0.f);
    float a = expf(l);
    g_aexp[e] = a;
    atomicAdd(&g_asum[dv], a);
}

__global__ __launch_bounds__(256) void k_ectx(const int* __restrict__ src,
                                              const int* __restrict__ dst, int E)
{
    int e = blockIdx.x * 8 + (threadIdx.x >> 5);
    if (e >= E) return;
    int lane = threadIdx.x & 31;
    int s = src[e], dv = dst[e];
    float w = g_aexp[e] / g_asum[dv];
    float4 h = *(const float4*)&g_hv[(size_t)s * DV + lane * 4];
    float* c = &g_ctx[(size_t)dv * DV + lane * 4];
    red4(c, w * h.x, w * h.y, w * h.z, w * h.w);
}

// ---------------- generic bf16x3 mma node GEMM ----------------
// C[M,N] = Asplit @ Bsplit^T + bias; A [M][K] hi/lo, B [N][K] hi/lo.
// CTA: 128 rows x 128 cols; 8 warps: rg=wid&3 (32 rows), chf=wid>>2 (64-col half).
#define ROWB 80
#define GA_H 0
#define GA_L 10240
#define GB_H 20480
#define GB_L 30720
#define GP   40960
#define GR   42496
// total static smem 44544

template<bool LNOUT>
__global__ __launch_bounds__(256, 2) void gemm_mma(
    const __nv_bfloat16* __restrict__ Ah, const __nv_bfloat16* __restrict__ Al,
    const __nv_bfloat16* __restrict__ Bh, const __nv_bfloat16* __restrict__ Bl,
    const float* __restrict__ bias, float* __restrict__ C,
    int M, int N, int K,
    const float* __restrict__ lnG, const float* __restrict__ lnB)
{
    __shared__ __align__(16) char sm[44544];
    u32 smb = smem_u32(sm);
    int tid = threadIdx.x;
    int wid = tid >> 5;
    int lane = tid & 31;
    int m0 = blockIdx.x * 128;
    int n0 = blockIdx.y * 128;
    int rg = wid & 3;
    int chf = wid >> 2;
    float* prm = (float*)(sm + GP);
    float2* redb = (float2*)(sm + GR);

    if (tid < 128) {
        prm[tid] = bias[n0 + tid];
        if (LNOUT) { prm[128 + tid] = lnG[tid]; prm[256 + tid] = lnB[tid]; }
    }

    float c[2][8][4];
    #pragma unroll
    for (int mt = 0; mt < 2; mt++)
        #pragma unroll
        for (int nt = 0; nt < 8; nt++)
            #pragma unroll
            for (int q = 0; q < 4; q++) c[mt][nt][q] = 0.f;

    int nch = K >> 5;
    for (int ch = 0; ch < nch; ch++) {
        #pragma unroll
        for (int rep = 0; rep < 2; rep++) {
            int i = tid + rep * 256;
            int row = i >> 2;
            int q = i & 3;
            int gr = m0 + row;
            uint4 vh = make_uint4(0, 0, 0, 0), vl = vh;
            if (gr < M) {
                vh = *(const uint4*)(Ah + (size_t)gr * K + ch * 32 + q * 8);
                vl = *(const uint4*)(Al + (size_t)gr * K + ch * 32 + q * 8);
            }
            *(uint4*)(sm + GA_H + row * ROWB + q * 16) = vh;
            *(uint4*)(sm + GA_L + row * ROWB + q * 16) = vl;
        }
        #pragma unroll
        for (int rep = 0; rep < 2; rep++) {
            int i = tid + rep * 256;
            int row = i >> 2;
            int q = i & 3;
            *(uint4*)(sm + GB_H + row * ROWB + q * 16) =
                *(const uint4*)(Bh + (size_t)(n0 + row) * K + ch * 32 + q * 8);
            *(uint4*)(sm + GB_L + row * ROWB + q * 16) =
                *(const uint4*)(Bl + (size_t)(n0 + row) * K + ch * 32 + q * 8);
        }
        __syncthreads();
        #pragma unroll
        for (int ks = 0; ks < 2; ks++) {
            u32 ah[2][4], al[2][4];
            #pragma unroll
            for (int mt = 0; mt < 2; mt++) {
                u32 abase = smb + GA_H
                          + (u32)(rg * 32 + mt * 16 + (lane & 15)) * ROWB
                          + (u32)(ks * 16 + (lane >> 4) * 8) * 2;
                ldsm4(ah[mt], abase);
                ldsm4(al[mt], abase + (GA_L - GA_H));
            }
            #pragma unroll
            for (int nt = 0; nt < 8; nt++) {
                u32 bbase = smb + GB_H
                          + (u32)(chf * 64 + nt * 8 + (lane & 7)) * ROWB
                          + (u32)(ks * 16 + ((lane >> 3) & 1) * 8) * 2;
                u32 bh[2], bl[2];
                ldsm2(bh, bbase);
                ldsm2(bl, bbase + (GB_L - GB_H));
                #pragma unroll
                for (int mt = 0; mt < 2; mt++) {
                    mma16816(c[mt][nt], ah[mt], bh);
                    mma16816(c[mt][nt], ah[mt], bl);
                    mma16816(c[mt][nt], al[mt], bh);
                }
            }
        }
        __syncthreads();
    }

    int quad = lane >> 2;
    int qlan = lane & 3;

    if (!LNOUT) {
        #pragma unroll
        for (int mt = 0; mt < 2; mt++) {
            int rl = rg * 32 + mt * 16 + quad;
            int rh = rl + 8;
            int grl = m0 + rl, grh = m0 + rh;
            #pragma unroll
            for (int nt = 0; nt < 8; nt++) {
                int col = chf * 64 + nt * 8 + qlan * 2;
                float b0 = prm[col], b1 = prm[col + 1];
                if (grl < M)
                    *(float2*)(C + (size_t)grl * N + n0 + col) =
                        make_float2(c[mt][nt][0] + b0, c[mt][nt][1] + b1);
                if (grh < M)
                    *(float2*)(C + (size_t)grh * N + n0 + col) =
                        make_float2(c[mt][nt][2] + b0, c[mt][nt][3] + b1);
            }
        }
    } else {
        // fused LN(128)+relu (N=128, grid.y=1)
        #pragma unroll
        for (int mt = 0; mt < 2; mt++) {
            int rl = rg * 32 + mt * 16 + quad;
            int rh = rl + 8;
            float sl = 0.f, ql = 0.f, sh = 0.f, qh = 0.f;
            #pragma unroll
            for (int nt = 0; nt < 8; nt++) {
                int col = chf * 64 + nt * 8 + qlan * 2;
                float p0 = c[mt][nt][0] + prm[col];
                float p1 = c[mt][nt][1] + prm[col + 1];
                float p2 = c[mt][nt][2] + prm[col];
                float p3 = c[mt][nt][3] + prm[col + 1];
                sl += p0 + p1; ql += p0 * p0 + p1 * p1;
                sh += p2 + p3; qh += p2 * p2 + p3 * p3;
            }
            sl += __shfl_xor_sync(0xffffffffu, sl, 1); sl += __shfl_xor_sync(0xffffffffu, sl, 2);
            ql += __shfl_xor_sync(0xffffffffu, ql, 1); ql += __shfl_xor_sync(0xffffffffu, ql, 2);
            sh += __shfl_xor_sync(0xffffffffu, sh, 1); sh += __shfl_xor_sync(0xffffffffu, sh, 2);
            qh += __shfl_xor_sync(0xffffffffu, qh, 1); qh += __shfl_xor_sync(0xffffffffu, qh, 2);
            if (qlan == 0) {
                redb[rl * 2 + chf] = make_float2(sl, ql);
                redb[rh * 2 + chf] = make_float2(sh, qh);
            }
        }
        __syncthreads();
        #pragma unroll
        for (int mt = 0; mt < 2; mt++) {
            int rl = rg * 32 + mt * 16 + quad;
            int rh = rl + 8;
            float2 t0 = redb[rl * 2 + 0], t1 = redb[rl * 2 + 1];
            float mul = (t0.x + t1.x) * (1.f / 128.f);
            float rsl = rsqrtf((t0.y + t1.y) * (1.f / 128.f) - mul * mul + LNEPS);
            float2 u0 = redb[rh * 2 + 0], u1 = redb[rh * 2 + 1];
            float muh = (u0.x + u1.x) * (1.f / 128.f);
            float rsh = rsqrtf((u0.y + u1.y) * (1.f / 128.f) - muh * muh + LNEPS);
            int grl = m0 + rl, grh = m0 + rh;
            #pragma unroll
            for (int nt = 0; nt < 8; nt++) {
                int col = chf * 64 + nt * 8 + qlan * 2;
                float gA = prm[128 + col], gB = prm[128 + col + 1];
                float bA = prm[256 + col], bB = prm[256 + col + 1];
                if (grl < M) {
                    float y0 = fmaxf((c[mt][nt][0] + prm[col] - mul) * rsl * gA + bA, 0.f);
                    float y1 = fmaxf((c[mt][nt][1] + prm[col + 1] - mul) * rsl * gB + bB, 0.f);
                    *(float2*)(C + (size_t)grl * 128 + col) = make_float2(y0, y1);
                }
                if (grh < M) {
                    float y2 = fmaxf((c[mt][nt][2] + prm[col] - muh) * rsh * gA + bA, 0.f);
                    float y3 = fmaxf((c[mt][nt][3] + prm[col + 1] - muh) * rsh * gB + bB, 0.f);
                    *(float2*)(C + (size_t)grh * 128 + col) = make_float2(y2, y3);
                }
            }
        }
    }
}

// ---------------- mma.sync kron (R15-proven) ----------------
#define SA_HI 0
#define SA_LO 10240
#define SB_HI 20480
#define SB_LO 30720
#define S_NPA 40960
#define S_NPB 51200
#define S_DST 61440
#define S_PRM 61952
#define S_RED 63488
#define KRON_SMEM 65536

__global__ __launch_bounds__(256, 2) void k_kron_mma(
    const int* __restrict__ src, const int* __restrict__ dst,
    const float* __restrict__ bk2,
    const float* __restrict__ g2, const float* __restrict__ beta2, int E)
{
    extern __shared__ __align__(16) char sm[];
    u32 smb = smem_u32(sm);
    int tid = threadIdx.x;
    int wid = tid >> 5;
    int lane = tid & 31;
    int e0 = blockIdx.x * 128;
    int rg = wid & 3;
    int chf = wid >> 2;

    float* npa = (float*)(sm + S_NPA);
    float* npb = (float*)(sm + S_NPB);
    int* dst_s = (int*)(sm + S_DST);
    float* prm = (float*)(sm + S_PRM);
    float2* redb = (float2*)(sm + S_RED);

    for (int idx = tid; idx < 128 * KP; idx += 256) {
        int e = idx / KP, c = idx - e * KP;
        int ge = e0 + e;
        float av = 0.f, bv = 0.f;
        if (ge < E) {
            av = g_npj[(size_t)src[ge] * KP + c];
            bv = g_npj[(size_t)dst[ge] * KP + c];
        }
        npa[e * KP + c] = av;
        npb[e * KP + c] = bv;
    }
    if (tid < 128) {
        dst_s[tid] = (e0 + tid < E) ? dst[e0 + tid] : 0;
        prm[tid] = bk2[tid];
        prm[128 + tid] = g2[tid];
        prm[256 + tid] = beta2[tid];
    }
    __syncthreads();

    float c[2][8][4];
    #pragma unroll
    for (int mt = 0; mt < 2; mt++)
        #pragma unroll
        for (int nt = 0; nt < 8; nt++)
            #pragma unroll
            for (int q = 0; q < 4; q++) c[mt][nt][q] = 0.f;

    int arow = tid >> 1;
    int akh = (tid & 1) * 16;
    const float* ar = npa + arow * KP;
    const float* br = npb + arow * KP;

    for (int ch = 0; ch < NCHUNK; ch++) {
        {
            u32 hw[8], lw[8];
            #pragma unroll
            for (int t4 = 0; t4 < 8; t4++) {
                u32 h2 = 0, l2 = 0;
                #pragma unroll
                for (int u = 0; u < 2; u++) {
                    int kk = ch * CH + akh + t4 * 2 + u;
                    float v = 0.f;
                    if (kk < KP * KP) {
                        int i = kk / KP;
                        int j = kk - i * KP;
                        v = ar[i] * br[j];
                    }
                    __nv_bfloat16 h = __float2bfloat16(v);
                    __nv_bfloat16 l = __float2bfloat16(v - __bfloat162float(h));
                    h2 |= (u32)__bfloat16_as_ushort(h) << (16 * u);
                    l2 |= (u32)__bfloat16_as_ushort(l) << (16 * u);
                }
                hw[t4] = h2; lw[t4] = l2;
            }
            char* pa = sm + SA_HI + arow * ROWB + akh * 2;
            char* pl = sm + SA_LO + arow * ROWB + akh * 2;
            *(uint4*)pa = *(uint4*)&hw[0];
            *(uint4*)(pa + 16) = *(uint4*)&hw[4];
            *(uint4*)pl = *(uint4*)&lw[0];
            *(uint4*)(pl + 16) = *(uint4*)&lw[4];
        }
        #pragma unroll
        for (int rep = 0; rep < 2; rep++) {
            int i = tid + rep * 256;
            int row = i >> 2;
            int q = i & 3;
            const uint4* srch = (const uint4*)(g_wbh + row * KPAD + ch * CH + q * 8);
            const uint4* srcl = (const uint4*)(g_wbl + row * KPAD + ch * CH + q * 8);
            *(uint4*)(sm + SB_HI + row * ROWB + q * 16) = *srch;
            *(uint4*)(sm + SB_LO + row * ROWB + q * 16) = *srcl;
        }
        __syncthreads();

        #pragma unroll
        for (int ks = 0; ks < 2; ks++) {
            u32 ah[2][4], al[2][4];
            #pragma unroll
            for (int mt = 0; mt < 2; mt++) {
                u32 abase = smb + SA_HI
                          + (u32)(rg * 32 + mt * 16 + (lane & 15)) * ROWB
                          + (u32)(ks * 16 + (lane >> 4) * 8) * 2;
                ldsm4(ah[mt], abase);
                ldsm4(al[mt], abase + (SA_LO - SA_HI));
            }
            #pragma unroll
            for (int nt = 0; nt < 8; nt++) {
                u32 bbase = smb + SB_HI
                          + (u32)(chf * 64 + nt * 8 + (lane & 7)) * ROWB
                          + (u32)(ks * 16 + ((lane >> 3) & 1) * 8) * 2;
                u32 bh[2], bl[2];
                ldsm2(bh, bbase);
                ldsm2(bl, bbase + (SB_LO - SB_HI));
                #pragma unroll
                for (int mt = 0; mt < 2; mt++) {
                    mma16816(c[mt][nt], ah[mt], bh);
                    mma16816(c[mt][nt], ah[mt], bl);
                    mma16816(c[mt][nt], al[mt], bh);
                }
            }
        }
        __syncthreads();
    }

    int quad = lane >> 2;
    int qlan = lane & 3;

    #pragma unroll
    for (int mt = 0; mt < 2; mt++) {
        int rl = rg * 32 + mt * 16 + quad;
        int rh = rl + 8;
        float sl = 0.f, ql = 0.f, sh = 0.f, qh = 0.f;
        #pragma unroll
        for (int nt = 0; nt < 8; nt++) {
            int col = chf * 64 + nt * 8 + qlan * 2;
            float p0 = c[mt][nt][0] + prm[col];
            float p1 = c[mt][nt][1] + prm[col + 1];
            float p2 = c[mt][nt][2] + prm[col];
            float p3 = c[mt][nt][3] + prm[col + 1];
            sl += p0 + p1; ql += p0 * p0 + p1 * p1;
            sh += p2 + p3; qh += p2 * p2 + p3 * p3;
        }
        sl += __shfl_xor_sync(0xffffffffu, sl, 1); sl += __shfl_xor_sync(0xffffffffu, sl, 2);
        ql += __shfl_xor_sync(0xffffffffu, ql, 1); ql += __shfl_xor_sync(0xffffffffu, ql, 2);
        sh += __shfl_xor_sync(0xffffffffu, sh, 1); sh += __shfl_xor_sync(0xffffffffu, sh, 2);
        qh += __shfl_xor_sync(0xffffffffu, qh, 1); qh += __shfl_xor_sync(0xffffffffu, qh, 2);
        if (qlan == 0) {
            redb[rl * 2 + chf] = make_float2(sl, ql);
            redb[rh * 2 + chf] = make_float2(sh, qh);
        }
    }
    __syncthreads();

    #pragma unroll
    for (int mt = 0; mt < 2; mt++) {
        int rl = rg * 32 + mt * 16 + quad;
        int rh = rl + 8;
        float2 t0 = redb[rl * 2 + 0], t1 = redb[rl * 2 + 1];
        float mul = (t0.x + t1.x) * (1.f / NOUT);
        float rsl = rsqrtf((t0.y + t1.y) * (1.f / NOUT) - mul * mul + LNEPS);
        float2 u0 = redb[rh * 2 + 0], u1 = redb[rh * 2 + 1];
        float muh = (u0.x + u1.x) * (1.f / NOUT);
        float rsh = rsqrtf((u0.y + u1.y) * (1.f / NOUT) - muh * muh + LNEPS);
        bool okl = (e0 + rl < E);
        bool okh = (e0 + rh < E);
        float* dl = g_kron + (size_t)dst_s[rl] * NOUT;
        float* dh = g_kron + (size_t)dst_s[rh] * NOUT;
        #pragma unroll
        for (int nt = 0; nt < 8; nt++) {
            int col = chf * 64 + nt * 8 + qlan * 2;
            float gA = prm[128 + col], gB = prm[128 + col + 1];
            float bA = prm[256 + col], bB = prm[256 + col + 1];
            if (okl) {
                float y0 = fmaxf((c[mt][nt][0] + prm[col] - mul) * rsl * gA + bA, 0.f);
                float y1 = fmaxf((c[mt][nt][1] + prm[col + 1] - mul) * rsl * gB + bB, 0.f);
                red2(dl + col, y0, y1);
            }
            if (okh) {
                float y2 = fmaxf((c[mt][nt][2] + prm[col] - muh) * rsh * gA + bA, 0.f);
                float y3 = fmaxf((c[mt][nt][3] + prm[col + 1] - muh) * rsh * gB + bB, 0.f);
                red2(dh + col, y2, y3);
            }
        }
    }
}

// ---------------- GRU combine + relu + LN(128) ----------------
__global__ __launch_bounds__(128) void k_gru(const float* __restrict__ nf,
                                             const float* __restrict__ lng,
                                             const float* __restrict__ lnb, int V)
{
    int v = blockIdx.x;
    int d = threadIdx.x;
    int wid = d >> 5, lane = d & 31;
    const float* gi = g_gi + (size_t)v * 3 * DV;
    const float* gh = g_gh + (size_t)v * 3 * DV;
    float r = 1.f / (1.f + expf(-(gi[d] + gh[d])));
    float z = 1.f / (1.f + expf(-(gi[DV + d] + gh[DV + d])));
    float nn = tanhf(gi[2 * DV + d] + r * gh[2 * DV + d]);
    float h = (1.f - z) * nn + z * nf[(size_t)v * DV + d];
    float x = fmaxf(h, 0.f);

    __shared__ float red[4];
    float s = warpSum32(x);
    if (lane == 0) red[wid] = s;
    __syncthreads();
    float mu = (red[0] + red[1] + red[2] + red[3]) * (1.f / DV);
    __syncthreads();
    float c = x - mu;
    float q = warpSum32(c * c);
    if (lane == 0) red[wid] = q;
    __syncthreads();
    float var = (red[0] + red[1] + red[2] + red[3]) * (1.f / DV);
    g_gru[(size_t)v * DV + d] = c * rsqrtf(var + LNEPS) * lng[d] + lnb[d];
}

// ---------------- host ----------------
static inline int cdiv(int a, int b) { return (a + b - 1) / b; }

extern "C" void kernel_launch(void* const* d_in, const int* in_sizes, int n_in,
                              void* d_out, int out_size)
{
    const float* nf     = (const float*)d_in[0];
    const int*   src    = (const int*)d_in[1];
    const int*   dst    = (const int*)d_in[2];
    const float* W_edge = (const float*)d_in[3];
    const float* b_edge = (const float*)d_in[4];
    const float* W_pn   = (const float*)d_in[5];
    const float* b_pn   = (const float*)d_in[6];
    const float* W_ih   = (const float*)d_in[7];
    const float* b_ih   = (const float*)d_in[8];
    const float* W_hh   = (const float*)d_in[9];
    const float* b_hh   = (const float*)d_in[10];
    const float* ln_g   = (const float*)d_in[11];
    const float* ln_b   = (const float*)d_in[12];
    const float* Wk1    = (const float*)d_in[13];
    const float* bk1    = (const float*)d_in[14];
    const float* lnk1_g = (const float*)d_in[15];
    const float* lnk1_b = (const float*)d_in[16];
    const float* Wk2    = (const float*)d_in[17];
    const float* bk2    = (const float*)d_in[18];
    const float* lnk2_g = (const float*)d_in[19];
    const float* lnk2_b = (const float*)d_in[20];
    const float* Wc     = (const float*)d_in[21];
    const float* bc     = (const float*)d_in[22];
    const float* lnc_g  = (const float*)d_in[23];
    const float* lnc_b  = (const float*)d_in[24];
    float* out = (float*)d_out;

    int V = in_sizes[0] / DV;
    int E = in_sizes[1];

    float *p_hv, *p_gh, *p_gi, *p_ctx;
    cudaGetSymbolAddress((void**)&p_hv,  g_hv);
    cudaGetSymbolAddress((void**)&p_gh,  g_gh);
    cudaGetSymbolAddress((void**)&p_gi,  g_gi);
    cudaGetSymbolAddress((void**)&p_ctx, g_ctx);
    __nv_bfloat16 *p_nfh, *p_nfl, *p_cxh, *p_cxl, *p_gkh, *p_gkl, *p_wsh, *p_wsl;
    cudaGetSymbolAddress((void**)&p_nfh, g_nfh);
    cudaGetSymbolAddress((void**)&p_nfl, g_nfl);
    cudaGetSymbolAddress((void**)&p_cxh, g_cxh);
    cudaGetSymbolAddress((void**)&p_cxl, g_cxl);
    cudaGetSymbolAddress((void**)&p_gkh, g_gkh);
    cudaGetSymbolAddress((void**)&p_gkl, g_gkl);
    cudaGetSymbolAddress((void**)&p_wsh, g_wsh);
    cudaGetSymbolAddress((void**)&p_wsl, g_wsl);

    cudaFuncSetAttribute(k_kron_mma, cudaFuncAttributeMaxDynamicSharedMemorySize, KRON_SMEM);

    int gx = cdiv(V, 128);

    k_zero<<<cdiv(V * DV, 256), 256>>>(V);
    k_wconv<<<cdiv(128 * KPAD, 256), 256>>>(Wk2);
    k_wsplit<<<cdiv(128 * 128, 256), 256>>>(W_pn, p_wsh,          p_wsl,          128, 128, 1);
    k_wsplit<<<cdiv(384 * 128, 256), 256>>>(W_hh, p_wsh + 16384,  p_wsl + 16384,  384, 128, 0);
    k_wsplit<<<cdiv(384 * 128, 256), 256>>>(W_ih, p_wsh + 65536,  p_wsl + 65536,  384, 128, 0);
    k_wsplit<<<cdiv(128 * 256, 256), 256>>>(Wc,   p_wsh + 114688, p_wsl + 114688, 128, 256, 1);
    k_split<<<cdiv(V * DV, 256), 256>>>(nf, p_nfh, p_nfl, V * DV, 0);
    k_node_pre<<<cdiv(V, 8), 256>>>(nf, Wk1, bk1, lnk1_g, lnk1_b, W_edge, V);

    // hv = nf @ W_pn + b_pn
    gemm_mma<false><<<dim3(gx, 1), 256>>>(p_nfh, p_nfl, p_wsh, p_wsl,
                                          b_pn, p_hv, V, 128, 128, nullptr, nullptr);
    // gh = nf @ W_hh^T + b_hh
    gemm_mma<false><<<dim3(gx, 3), 256>>>(p_nfh, p_nfl, p_wsh + 16384, p_wsl + 16384,
                                          b_hh, p_gh, V, 384, 128, nullptr, nullptr);

    k_eatt<<<cdiv(E, 256), 256>>>(src, dst, b_edge, E);
    k_ectx<<<cdiv(E, 8), 256>>>(src, dst, E);

    k_kron_mma<<<cdiv(E, 128), 256, KRON_SMEM>>>(src, dst, bk2, lnk2_g, lnk2_b, E);

    // gi = relu(ctx) @ W_ih^T + b_ih
    k_split<<<cdiv(V * DV, 256), 256>>>(p_ctx, p_cxh, p_cxl, V * DV, 1);
    gemm_mma<false><<<dim3(gx, 3), 256>>>(p_cxh, p_cxl, p_wsh + 65536, p_wsl + 65536,
                                          b_ih, p_gi, V, 384, 128, nullptr, nullptr);

    k_gru<<<V, 128>>>(nf, ln_g, ln_b, V);

    // out = relu(LN([gru, kron] @ Wc + bc))
    k_split_gk<<<cdiv(V * 2 * DV, 256), 256>>>(V);
    gemm_mma<true><<<dim3(gx, 1), 256>>>(p_gkh, p_gkl, p_wsh + 114688, p_wsl + 114688,
                                         bc, out, V, 128, 256, lnc_g, lnc_b);
}